// round 1
// baseline (speedup 1.0000x reference)
#include <cuda_runtime.h>
#include <cstdint>

#define BB 4
#define NN 2048
#define KK 16
#define DD 64
#define NK (NN*KK)
#define EPSV 1e-5f

// ---------------- scratch (device globals; no allocation allowed) ----------------
__device__ float g_h  [BB*DD*NN];
__device__ float g_x  [BB*DD*NN];
__device__ float g_q  [BB*DD*NN];
__device__ float g_k  [BB*DD*NN];
__device__ float g_v  [BB*DD*NN];
__device__ float g_qt [BB*NN*DD];
__device__ float g_kt [BB*NN*DD];
__device__ float g_vt [BB*NN*DD];
__device__ int   g_idx[BB*KK*NN];
__device__ float g_rel[BB*3*NN*KK];
__device__ float g_t1 [BB*DD*NK];
__device__ float g_pos[BB*DD*NK];
__device__ float g_G  [BB*DD*NK];
__device__ float g_vr [BB*DD*NK];
__device__ float g_H  [(size_t)BB*256*NK];
__device__ float g_at [BB*DD*NK];
__device__ float g_ch [BB*DD*4*NN];
__device__ float g_fold[640];       // [0:64) s_fd, [64:128) b_fd, [128:384) s_fg, [384:640) b_fg
__device__ float g_wT[4*64*64];     // at_w transposed to [r][c][o]

// ---------------- prep: fold BN into conv bias/scale; transpose at_w ----------------
__global__ void prep_kernel(const float* __restrict__ fd_g, const float* __restrict__ fd1_b,
                            const float* __restrict__ fd_bb,
                            const float* __restrict__ fg_g, const float* __restrict__ fg1_b,
                            const float* __restrict__ fg_bb,
                            const float* __restrict__ at_w)
{
    int t = blockIdx.x * blockDim.x + threadIdx.x;
    float inv = rsqrtf(1.f + EPSV);
    if (t < 64)  { float s = fd_g[t]*inv; g_fold[t] = s;       g_fold[64+t]  = fd1_b[t]*s + fd_bb[t]; }
    if (t < 256) { float s = fg_g[t]*inv; g_fold[128+t] = s;   g_fold[384+t] = fg1_b[t]*s + fg_bb[t]; }
    if (t < 16384) {
        int r = t & 3; int o = (t >> 2) & 63; int c = t >> 8;
        g_wT[r*4096 + c*64 + o] = at_w[t];   // at_w[c][o][r] row-major
    }
}

// ---------------- KNN: warp per point, per-lane top-17 + warp merge ----------------
__global__ void knn_kernel(const float* __restrict__ xyz)
{
    __shared__ float sx[NN], sy[NN], sz[NN], ssq[NN];
    int b  = blockIdx.x >> 7;            // 128 blocks per batch
    int n0 = (blockIdx.x & 127) * 16;    // 16 warps per block
    const float* xb = xyz + b*3*NN;
    for (int m = threadIdx.x; m < NN; m += blockDim.x) {
        float px = xb[m], py = xb[NN+m], pz = xb[2*NN+m];
        sx[m]=px; sy[m]=py; sz[m]=pz; ssq[m] = px*px + py*py + pz*pz;
    }
    __syncthreads();
    int warp = threadIdx.x >> 5, lane = threadIdx.x & 31;
    int n = n0 + warp;
    float px = sx[n], py = sy[n], pz = sz[n], sqn = ssq[n];

    float bv[17]; int bi[17];
    #pragma unroll
    for (int i = 0; i < 17; i++) { bv[i] = 3.4e38f; bi[i] = 0x7fffffff; }

    for (int m = lane; m < NN; m += 32) {
        float d2 = sqn + ssq[m] - 2.f*(px*sx[m] + py*sy[m] + pz*sz[m]);
        if (d2 < bv[16]) {
            bv[16] = d2; bi[16] = m;
            #pragma unroll
            for (int s = 16; s > 0; --s) {
                if (bv[s] < bv[s-1]) {
                    float tv = bv[s]; bv[s] = bv[s-1]; bv[s-1] = tv;
                    int   ti = bi[s]; bi[s] = bi[s-1]; bi[s-1] = ti;
                }
            }
        }
    }
    // merge: 17 rounds of warp lexicographic argmin; round 0 = self, dropped
    for (int t = 0; t < 17; ++t) {
        float hv = bv[0]; int hi = bi[0];
        float v = hv; int id = hi;
        #pragma unroll
        for (int off = 16; off; off >>= 1) {
            float ov = __shfl_xor_sync(0xffffffffu, v, off);
            int   oi = __shfl_xor_sync(0xffffffffu, id, off);
            if (ov < v || (ov == v && oi < id)) { v = ov; id = oi; }
        }
        if (t > 0 && lane == 0) g_idx[b*KK*NN + (t-1)*NN + n] = id;
        if (hv == v && hi == id) {
            #pragma unroll
            for (int s = 0; s < 16; ++s) { bv[s] = bv[s+1]; bi[s] = bi[s+1]; }
            bv[16] = 3.4e38f; bi[16] = 0x7fffffff;
        }
    }
}

// ---------------- generic fp32 GEMM: C[b] = epi(W(MxK) @ X[b](KxNc)) ----------------
// epi: v = acc*scale[m] (opt) + bias[m]; v += S (opt); relu (opt)
template<bool RELU, bool ADD, bool SCALE>
__global__ __launch_bounds__(256) void gemm_kernel(
    const float* __restrict__ W, const float* __restrict__ X,
    const float* __restrict__ scale, const float* __restrict__ bias,
    const float* __restrict__ S, float* __restrict__ C,
    int M, int Kd, int Nc)
{
    __shared__ float sW[16][68];
    __shared__ float sX[16][132];
    int tid = threadIdx.x;
    int tx = tid & 15;
    int ty = tid >> 4;
    int bn0 = blockIdx.x * 128;
    int bm0 = blockIdx.y * 64;
    const float* Xb = X + (size_t)blockIdx.z * Kd * Nc;
    size_t coff = (size_t)blockIdx.z * M * Nc;

    float acc[4][8];
    #pragma unroll
    for (int i = 0; i < 4; i++)
        #pragma unroll
        for (int j = 0; j < 8; j++) acc[i][j] = 0.f;

    for (int k0 = 0; k0 < Kd; k0 += 16) {
        #pragma unroll
        for (int i = tid; i < 1024; i += 256) {
            int m = i >> 4, k = i & 15;
            float val = 0.f;
            if (bm0 + m < M && k0 + k < Kd) val = W[(bm0+m)*Kd + k0 + k];
            sW[k][m] = val;
        }
        #pragma unroll
        for (int i = tid; i < 2048; i += 256) {
            int k = i >> 7, nn = i & 127;
            float val = 0.f;
            if (k0 + k < Kd) val = Xb[(size_t)(k0+k)*Nc + bn0 + nn];
            sX[k][nn] = val;
        }
        __syncthreads();
        #pragma unroll
        for (int k = 0; k < 16; k++) {
            float a[4], bb[8];
            #pragma unroll
            for (int i = 0; i < 4; i++) a[i] = sW[k][ty + 16*i];
            #pragma unroll
            for (int j = 0; j < 8; j++) bb[j] = sX[k][tx + 16*j];
            #pragma unroll
            for (int i = 0; i < 4; i++)
                #pragma unroll
                for (int j = 0; j < 8; j++) acc[i][j] = fmaf(a[i], bb[j], acc[i][j]);
        }
        __syncthreads();
    }
    #pragma unroll
    for (int i = 0; i < 4; i++) {
        int m = bm0 + ty + 16*i;
        if (m >= M) continue;
        float sc = SCALE ? scale[m] : 1.f;
        float bs = bias[m];
        #pragma unroll
        for (int j = 0; j < 8; j++) {
            int nn = bn0 + tx + 16*j;
            float v = acc[i][j]*sc + bs;
            if (ADD)  v += S[coff + (size_t)m*Nc + nn];
            if (RELU) v = fmaxf(v, 0.f);
            C[coff + (size_t)m*Nc + nn] = v;
        }
    }
}

// ---------------- transpose (B,64,2048) -> (B,2048,64) ----------------
__global__ void transpose_k(const float* __restrict__ src, float* __restrict__ dst)
{
    __shared__ float tile[32][33];
    int b = blockIdx.z;
    int n0 = blockIdx.x*32, c0 = blockIdx.y*32;
    const float* s = src + (size_t)b*DD*NN;
    float* d = dst + (size_t)b*NN*DD;
    for (int i = threadIdx.y; i < 32; i += 8)
        tile[i][threadIdx.x] = s[(c0+i)*NN + n0 + threadIdx.x];
    __syncthreads();
    for (int i = threadIdx.y; i < 32; i += 8)
        d[(n0+i)*DD + c0 + threadIdx.x] = tile[threadIdx.x][i];
}

// ---------------- rel_xyz gather: (b,3,n,j) layout ----------------
__global__ void rel_build(const float* __restrict__ xyz)
{
    int t = blockIdx.x*blockDim.x + threadIdx.x;
    if (t >= BB*NN*KK) return;
    int j = t & 15; int n = (t >> 4) & 2047; int b = t >> 15;
    int id = g_idx[b*KK*NN + j*NN + n];
    #pragma unroll
    for (int d = 0; d < 3; d++) {
        float vv = xyz[(b*3+d)*NN + n] - xyz[(b*3+d)*NN + id];
        g_rel[((size_t)(b*3+d)*NN + n)*KK + j] = vv;
    }
}

// ---------------- G = q - k_gather + pos ; Vrel = v_gather + pos ----------------
__global__ void gv_build()
{
    int t = blockIdx.x*blockDim.x + threadIdx.x;
    if (t >= BB*NN*KK) return;
    int j = t & 15; int n = (t >> 4) & 2047; int b = t >> 15;
    int id = g_idx[b*KK*NN + j*NN + n];
    const float* qt = g_qt + ((size_t)b*NN + n )*DD;
    const float* kt = g_kt + ((size_t)b*NN + id)*DD;
    const float* vt = g_vt + ((size_t)b*NN + id)*DD;
    #pragma unroll 4
    for (int c = 0; c < DD; c++) {
        size_t off = ((size_t)(b*DD + c)*NN + n)*KK + j;
        float p = g_pos[off];
        g_G[off]  = qt[c] - kt[c] + p;
        g_vr[off] = vt[c] + p;
    }
}

// ---------------- fused ConvTranspose(4,1) + channel-softmax + weighted sum + identity ----------------
// block = (b,n); 256 threads: o = tid&63 (channel), r = tid>>6 (upsample phase)
__global__ __launch_bounds__(256) void k4_kernel(const float* __restrict__ at_b,
                                                 float* __restrict__ res_out)
{
    __shared__ float s_a[64*16];     // [c][f]
    __shared__ float s_v[16*64];     // [f][c]
    __shared__ float s_m[16][8];
    __shared__ float s_s[16][8];
    __shared__ float s_out[256];
    int bn = blockIdx.x;
    int b = bn >> 11, n = bn & 2047;
    int tid = threadIdx.x;
    int o = tid & 63, r = tid >> 6;
    int lane = tid & 31, warp = tid >> 5;
    {
        int c = tid >> 2, fq = (tid & 3) * 4;
        size_t base = ((size_t)(b*64 + c)*2048 + n)*16 + fq;
        float4 a4 = *(const float4*)(g_at + base);
        *(float4*)(s_a + c*16 + fq) = a4;
        float4 v4 = *(const float4*)(g_vr + base);
        s_v[(fq+0)*64 + c] = v4.x;
        s_v[(fq+1)*64 + c] = v4.y;
        s_v[(fq+2)*64 + c] = v4.z;
        s_v[(fq+3)*64 + c] = v4.w;
    }
    __syncthreads();

    float y[16];
    float bo = at_b[o];
    #pragma unroll
    for (int f = 0; f < 16; f++) y[f] = bo;
    const float* w = g_wT + r*4096 + o;
    #pragma unroll 4
    for (int c = 0; c < 64; c++) {
        float wv = w[c*64];
        const float4* ap = (const float4*)(s_a + c*16);
        float4 a0 = ap[0], a1 = ap[1], a2 = ap[2], a3 = ap[3];
        y[0]  = fmaf(wv, a0.x, y[0]);  y[1]  = fmaf(wv, a0.y, y[1]);
        y[2]  = fmaf(wv, a0.z, y[2]);  y[3]  = fmaf(wv, a0.w, y[3]);
        y[4]  = fmaf(wv, a1.x, y[4]);  y[5]  = fmaf(wv, a1.y, y[5]);
        y[6]  = fmaf(wv, a1.z, y[6]);  y[7]  = fmaf(wv, a1.w, y[7]);
        y[8]  = fmaf(wv, a2.x, y[8]);  y[9]  = fmaf(wv, a2.y, y[9]);
        y[10] = fmaf(wv, a2.z, y[10]); y[11] = fmaf(wv, a2.w, y[11]);
        y[12] = fmaf(wv, a3.x, y[12]); y[13] = fmaf(wv, a3.y, y[13]);
        y[14] = fmaf(wv, a3.z, y[14]); y[15] = fmaf(wv, a3.w, y[15]);
    }
    // softmax over o (64 threads = warps 2r, 2r+1), batched reductions
    #pragma unroll
    for (int f = 0; f < 16; f++) {
        float m = y[f];
        #pragma unroll
        for (int off = 16; off; off >>= 1) m = fmaxf(m, __shfl_xor_sync(0xffffffffu, m, off));
        if (lane == 0) s_m[f][warp] = m;
    }
    __syncthreads();
    #pragma unroll
    for (int f = 0; f < 16; f++) {
        float m = fmaxf(s_m[f][2*r], s_m[f][2*r+1]);
        float e = __expf(y[f] - m);
        y[f] = e;
        float sm = e;
        #pragma unroll
        for (int off = 16; off; off >>= 1) sm += __shfl_xor_sync(0xffffffffu, sm, off);
        if (lane == 0) s_s[f][warp] = sm;
    }
    __syncthreads();
    float acc = 0.f;
    #pragma unroll
    for (int f = 0; f < 16; f++) {
        float sum = s_s[f][2*r] + s_s[f][2*r+1];
        acc = fmaf(y[f] / sum, s_v[f*64 + o], acc);
    }
    acc += g_x[(size_t)b*131072 + o*2048 + n];
    s_out[o*4 + r] = acc;
    __syncthreads();
    if (tid < 64) {
        float4 ov = *(const float4*)(s_out + tid*4);
        *(float4*)(res_out + (size_t)b*524288 + (size_t)tid*8192 + n*4) = ov;
    }
}

// ---------------- launch ----------------
extern "C" void kernel_launch(void* const* d_in, const int* in_sizes, int n_in,
                              void* d_out, int out_size)
{
    const float* feature = (const float*)d_in[0];
    const float* xyz     = (const float*)d_in[1];
    const float* bt1_w = (const float*)d_in[2];  const float* bt1_b = (const float*)d_in[3];
    const float* bt2_w = (const float*)d_in[4];  const float* bt2_b = (const float*)d_in[5];
    const float* bts_w = (const float*)d_in[6];  const float* bts_b = (const float*)d_in[7];
    const float* q_w   = (const float*)d_in[8];  const float* q_b   = (const float*)d_in[9];
    const float* k_w   = (const float*)d_in[10]; const float* k_b   = (const float*)d_in[11];
    const float* v_w   = (const float*)d_in[12]; const float* v_b   = (const float*)d_in[13];
    const float* fd1_w = (const float*)d_in[14]; const float* fd1_b = (const float*)d_in[15];
    const float* fd_g  = (const float*)d_in[16]; const float* fd_bb = (const float*)d_in[17];
    const float* fd2_w = (const float*)d_in[18]; const float* fd2_b = (const float*)d_in[19];
    const float* fg1_w = (const float*)d_in[20]; const float* fg1_b = (const float*)d_in[21];
    const float* fg_g  = (const float*)d_in[22]; const float* fg_bb = (const float*)d_in[23];
    const float* fg2_w = (const float*)d_in[24]; const float* fg2_b = (const float*)d_in[25];
    const float* at_w  = (const float*)d_in[26]; const float* at_b  = (const float*)d_in[27];
    const float* m41_w = (const float*)d_in[28]; const float* m41_b = (const float*)d_in[29];
    const float* m42_w = (const float*)d_in[30]; const float* m42_b = (const float*)d_in[31];

    float *ph, *px, *pq, *pk, *pv, *pqt, *pkt, *pvt, *pt1, *ppos, *pG, *pH, *pat, *pch, *pfold;
    cudaGetSymbolAddress((void**)&ph,   g_h);
    cudaGetSymbolAddress((void**)&px,   g_x);
    cudaGetSymbolAddress((void**)&pq,   g_q);
    cudaGetSymbolAddress((void**)&pk,   g_k);
    cudaGetSymbolAddress((void**)&pv,   g_v);
    cudaGetSymbolAddress((void**)&pqt,  g_qt);
    cudaGetSymbolAddress((void**)&pkt,  g_kt);
    cudaGetSymbolAddress((void**)&pvt,  g_vt);
    cudaGetSymbolAddress((void**)&pt1,  g_t1);
    cudaGetSymbolAddress((void**)&ppos, g_pos);
    cudaGetSymbolAddress((void**)&pG,   g_G);
    cudaGetSymbolAddress((void**)&pH,   g_H);
    cudaGetSymbolAddress((void**)&pat,  g_at);
    cudaGetSymbolAddress((void**)&pch,  g_ch);
    cudaGetSymbolAddress((void**)&pfold,g_fold);
    float* prel; cudaGetSymbolAddress((void**)&prel, g_rel);

    float* out = (float*)d_out;
    float* res = out + BB*3*4*NN;   // completion first (98304 floats), then res

    prep_kernel<<<64, 256>>>(fd_g, fd1_b, fd_bb, fg_g, fg1_b, fg_bb, at_w);
    knn_kernel<<<BB*NN/16, 512>>>(xyz);

    // x = mlp_res(feature)
    gemm_kernel<true,false,false><<<dim3(16,1,BB),256>>>(bt1_w, feature, nullptr, bt1_b, nullptr, ph, 64, 480, NN);
    gemm_kernel<false,false,false><<<dim3(16,1,BB),256>>>(bts_w, feature, nullptr, bts_b, nullptr, px, 64, 480, NN);
    gemm_kernel<false,true,false><<<dim3(16,1,BB),256>>>(bt2_w, ph, nullptr, bt2_b, px, px, 64, 64, NN);

    // q, k, v
    gemm_kernel<false,false,false><<<dim3(16,1,BB),256>>>(q_w, px, nullptr, q_b, nullptr, pq, 64, 64, NN);
    gemm_kernel<false,false,false><<<dim3(16,1,BB),256>>>(k_w, px, nullptr, k_b, nullptr, pk, 64, 64, NN);
    gemm_kernel<false,false,false><<<dim3(16,1,BB),256>>>(v_w, px, nullptr, v_b, nullptr, pv, 64, 64, NN);
    transpose_k<<<dim3(64,2,BB), dim3(32,8)>>>(pq, pqt);
    transpose_k<<<dim3(64,2,BB), dim3(32,8)>>>(pk, pkt);
    transpose_k<<<dim3(64,2,BB), dim3(32,8)>>>(pv, pvt);

    // pos_enc
    rel_build<<<512, 256>>>(xyz);
    gemm_kernel<true,false,true><<<dim3(256,1,BB),256>>>(fd1_w, prel, pfold, pfold+64, nullptr, pt1, 64, 3, NK);
    gemm_kernel<false,false,false><<<dim3(256,1,BB),256>>>(fd2_w, pt1, nullptr, fd2_b, nullptr, ppos, 64, 64, NK);

    // attention MLP
    gv_build<<<512, 256>>>();
    gemm_kernel<true,false,true><<<dim3(256,4,BB),256>>>(fg1_w, pG, pfold+128, pfold+384, nullptr, pH, 256, 64, NK);
    gemm_kernel<false,false,false><<<dim3(256,1,BB),256>>>(fg2_w, pH, nullptr, fg2_b, nullptr, pat, 64, 256, NK);

    // fused upsample-attention + identity -> res (written to d_out)
    k4_kernel<<<BB*NN, 256>>>(at_b, res);

    // completion head
    gemm_kernel<true,false,false><<<dim3(64,1,BB),256>>>(m41_w, res, nullptr, m41_b, nullptr, pch, 64, 64, 4*NN);
    gemm_kernel<false,false,false><<<dim3(64,1,BB),256>>>(m42_w, pch, nullptr, m42_b, nullptr, out, 3, 64, 4*NN);
}

// round 2
// speedup vs baseline: 1.2698x; 1.2698x over previous
#include <cuda_runtime.h>
#include <cstdint>

#define BB 4
#define NN 2048
#define KK 16
#define DD 64
#define NK (NN*KK)
#define EPSV 1e-5f

// ---------------- scratch (device globals) ----------------
__device__ float g_hx  [BB*128*NN];          // stacked [h(0:64); xs(64:128)]
__device__ float g_x   [BB*DD*NN];
__device__ float g_qkv [BB*192*NN];          // [b][192][n]
__device__ float g_qkvt[BB*NN*192];          // [b][n][192] (q,k,v)
__device__ int   g_idx [BB*KK*NN];
__device__ float g_t1  [BB*DD*NK];
__device__ float g_pos [BB*DD*NK];
__device__ float g_G   [BB*DD*NK];
__device__ float g_vr  [BB*DD*NK];
__device__ float g_H   [(size_t)BB*256*NK];
__device__ float g_at  [BB*DD*NK];
__device__ float g_ch  [BB*DD*4*NN];
__device__ float g_fold[640];                // [0:64) s_fd [64:128) b_fd [128:384) s_fg [384:640) b_fg
__device__ float g_wT  [4*64*64];            // at_w -> [r][c][o]
// pre-transposed weights [K][M]
__device__ float g_w_bt1s[480*128];
__device__ float g_b_bt1s[128];
__device__ float g_w_bt2 [64*64];
__device__ float g_w_qkv [64*192];
__device__ float g_b_qkv [192];
__device__ float g_w_fd2 [64*64];
__device__ float g_w_fg1 [64*256];
__device__ float g_w_fg2 [256*64];
__device__ float g_w_m41 [64*64];

// ---------------- prep: fold BN, transpose all weights ----------------
__global__ void prep_kernel(const float* __restrict__ fd_g, const float* __restrict__ fd1_b,
                            const float* __restrict__ fd_bb,
                            const float* __restrict__ fg_g, const float* __restrict__ fg1_b,
                            const float* __restrict__ fg_bb,
                            const float* __restrict__ at_w,
                            const float* __restrict__ bt1_w, const float* __restrict__ bt1_b,
                            const float* __restrict__ bts_w, const float* __restrict__ bts_b,
                            const float* __restrict__ bt2_w,
                            const float* __restrict__ q_w, const float* __restrict__ q_b,
                            const float* __restrict__ k_w, const float* __restrict__ k_b,
                            const float* __restrict__ v_w, const float* __restrict__ v_b,
                            const float* __restrict__ fd2_w,
                            const float* __restrict__ fg1_w, const float* __restrict__ fg2_w,
                            const float* __restrict__ m41_w)
{
    int t = blockIdx.x * blockDim.x + threadIdx.x;
    float inv = rsqrtf(1.f + EPSV);
    if (t < 64)  { float s = fd_g[t]*inv; g_fold[t] = s;     g_fold[64+t]  = fd1_b[t]*s + fd_bb[t]; }
    if (t < 256) { float s = fg_g[t]*inv; g_fold[128+t] = s; g_fold[384+t] = fg1_b[t]*s + fg_bb[t]; }
    if (t < 16384) {
        int r = t & 3, o = (t >> 2) & 63, c = t >> 8;
        g_wT[r*4096 + c*64 + o] = at_w[t];                   // at_w[c][o][r]
        { int k = t >> 8, m = t & 255; g_w_fg1[k*256 + m] = fg1_w[m*64 + k]; }
        { int k = t >> 6, m = t & 63;  g_w_fg2[k*64 + m]  = fg2_w[m*256 + k]; }
    }
    if (t < 61440) { int k = t >> 7, m = t & 127;
        g_w_bt1s[t] = (m < 64) ? bt1_w[m*480 + k] : bts_w[(m-64)*480 + k]; }
    if (t < 128) g_b_bt1s[t] = (t < 64) ? bt1_b[t] : bts_b[t-64];
    if (t < 12288) { int k = t / 192, m = t % 192;
        g_w_qkv[t] = (m < 64) ? q_w[m*64+k] : (m < 128 ? k_w[(m-64)*64+k] : v_w[(m-128)*64+k]); }
    if (t < 192) g_b_qkv[t] = (t < 64) ? q_b[t] : (t < 128 ? k_b[t-64] : v_b[t-128]);
    if (t < 4096) { int k = t >> 6, m = t & 63;
        g_w_bt2[t] = bt2_w[m*64+k];
        g_w_fd2[t] = fd2_w[m*64+k];
        g_w_m41[t] = m41_w[m*64+k]; }
}

// ---------------- KNN: warp per point ----------------
__global__ void knn_kernel(const float* __restrict__ xyz)
{
    __shared__ float sx[NN], sy[NN], sz[NN], ssq[NN];
    int b  = blockIdx.x >> 7;
    int n0 = (blockIdx.x & 127) * 16;
    const float* xb = xyz + b*3*NN;
    for (int m = threadIdx.x; m < NN; m += blockDim.x) {
        float px = xb[m], py = xb[NN+m], pz = xb[2*NN+m];
        sx[m]=px; sy[m]=py; sz[m]=pz; ssq[m] = px*px + py*py + pz*pz;
    }
    __syncthreads();
    int warp = threadIdx.x >> 5, lane = threadIdx.x & 31;
    int n = n0 + warp;
    float px = sx[n], py = sy[n], pz = sz[n], sqn = ssq[n];

    float bv[17]; int bi[17];
    #pragma unroll
    for (int i = 0; i < 17; i++) { bv[i] = 3.4e38f; bi[i] = 0x7fffffff; }
    for (int m = lane; m < NN; m += 32) {
        float d2 = sqn + ssq[m] - 2.f*(px*sx[m] + py*sy[m] + pz*sz[m]);
        if (d2 < bv[16]) {
            bv[16] = d2; bi[16] = m;
            #pragma unroll
            for (int s = 16; s > 0; --s)
                if (bv[s] < bv[s-1]) {
                    float tv = bv[s]; bv[s] = bv[s-1]; bv[s-1] = tv;
                    int   ti = bi[s]; bi[s] = bi[s-1]; bi[s-1] = ti;
                }
        }
    }
    for (int t = 0; t < 17; ++t) {
        float hv = bv[0]; int hi = bi[0];
        float v = hv; int id = hi;
        #pragma unroll
        for (int off = 16; off; off >>= 1) {
            float ov = __shfl_xor_sync(0xffffffffu, v, off);
            int   oi = __shfl_xor_sync(0xffffffffu, id, off);
            if (ov < v || (ov == v && oi < id)) { v = ov; id = oi; }
        }
        if (t > 0 && lane == 0) g_idx[b*KK*NN + (t-1)*NN + n] = id;
        if (hv == v && hi == id) {
            #pragma unroll
            for (int s = 0; s < 16; ++s) { bv[s] = bv[s+1]; bi[s] = bi[s+1]; }
            bv[16] = 3.4e38f; bi[16] = 0x7fffffff;
        }
    }
}

// ---------------- tiled fp32 GEMM, Wt pre-transposed [K][M], 8x8 reg tiles ----------------
template<int BM, int BN, bool ADD, bool SCALE>
__global__ void __launch_bounds__((BM/8)*(BN/8))
gemmT(const float* __restrict__ Wt, int ldw,
      const float* __restrict__ X, size_t xbs,
      const float* __restrict__ scale, const float* __restrict__ bias,
      const float* __restrict__ S, size_t sbs,
      float* __restrict__ C, size_t cbs,
      int Kd, int Nc, int relu_rows)
{
    constexpr int KC = 8;
    constexpr int NTH = (BM/8)*(BN/8);
    constexpr int W4 = KC*BM/4, X4 = KC*BN/4;
    constexpr int WPT = (W4 + NTH - 1)/NTH, XPT = (X4 + NTH - 1)/NTH;
    __shared__ __align__(16) float sW[2][KC][BM];
    __shared__ __align__(16) float sX[2][KC][BN];
    int tid = threadIdx.x;
    int bn0 = blockIdx.x * BN;
    int bm0 = blockIdx.y * BM;
    const float* Xb = X + (size_t)blockIdx.z * xbs;
    const float* Sb = S ? S + (size_t)blockIdx.z * sbs : nullptr;
    float* Cb = C + (size_t)blockIdx.z * cbs;

    float4 wr[WPT], xr[XPT];
    float acc[8][8] = {};
    int tx = tid % (BN/8), ty = tid / (BN/8);
    int rm = ty*8, rn = tx*8;
    int nch = Kd / KC;

    // fetch chunk 0
    {
        #pragma unroll
        for (int i = 0; i < WPT; i++) { int t = tid + i*NTH; if (t < W4) {
            int k = t/(BM/4), m4 = t%(BM/4);
            wr[i] = *(const float4*)(Wt + (size_t)k*ldw + bm0 + m4*4); } }
        #pragma unroll
        for (int i = 0; i < XPT; i++) { int t = tid + i*NTH; if (t < X4) {
            int k = t/(BN/4), n4 = t%(BN/4);
            xr[i] = *(const float4*)(Xb + (size_t)k*Nc + bn0 + n4*4); } }
        #pragma unroll
        for (int i = 0; i < WPT; i++) { int t = tid + i*NTH; if (t < W4) {
            int k = t/(BM/4), m4 = t%(BM/4); *(float4*)&sW[0][k][m4*4] = wr[i]; } }
        #pragma unroll
        for (int i = 0; i < XPT; i++) { int t = tid + i*NTH; if (t < X4) {
            int k = t/(BN/4), n4 = t%(BN/4); *(float4*)&sX[0][k][n4*4] = xr[i]; } }
    }
    __syncthreads();

    for (int c = 0; c < nch; ++c) {
        if (c + 1 < nch) {
            int k0 = (c+1)*KC;
            #pragma unroll
            for (int i = 0; i < WPT; i++) { int t = tid + i*NTH; if (t < W4) {
                int k = t/(BM/4), m4 = t%(BM/4);
                wr[i] = *(const float4*)(Wt + (size_t)(k0+k)*ldw + bm0 + m4*4); } }
            #pragma unroll
            for (int i = 0; i < XPT; i++) { int t = tid + i*NTH; if (t < X4) {
                int k = t/(BN/4), n4 = t%(BN/4);
                xr[i] = *(const float4*)(Xb + (size_t)(k0+k)*Nc + bn0 + n4*4); } }
        }
        int buf = c & 1;
        #pragma unroll
        for (int k = 0; k < KC; ++k) {
            float4 a0 = *(const float4*)&sW[buf][k][rm];
            float4 a1 = *(const float4*)&sW[buf][k][rm+4];
            float4 b0 = *(const float4*)&sX[buf][k][rn];
            float4 b1 = *(const float4*)&sX[buf][k][rn+4];
            float a[8] = {a0.x,a0.y,a0.z,a0.w,a1.x,a1.y,a1.z,a1.w};
            float bb[8] = {b0.x,b0.y,b0.z,b0.w,b1.x,b1.y,b1.z,b1.w};
            #pragma unroll
            for (int i = 0; i < 8; i++)
                #pragma unroll
                for (int j = 0; j < 8; j++) acc[i][j] = fmaf(a[i], bb[j], acc[i][j]);
        }
        if (c + 1 < nch) {
            int nb = (c+1) & 1;
            #pragma unroll
            for (int i = 0; i < WPT; i++) { int t = tid + i*NTH; if (t < W4) {
                int k = t/(BM/4), m4 = t%(BM/4); *(float4*)&sW[nb][k][m4*4] = wr[i]; } }
            #pragma unroll
            for (int i = 0; i < XPT; i++) { int t = tid + i*NTH; if (t < X4) {
                int k = t/(BN/4), n4 = t%(BN/4); *(float4*)&sX[nb][k][n4*4] = xr[i]; } }
        }
        __syncthreads();
    }

    #pragma unroll
    for (int i = 0; i < 8; i++) {
        int row = bm0 + rm + i;
        float sc = SCALE ? scale[row] : 1.f;
        float bs = bias[row];
        bool rl = row < relu_rows;
        float v[8];
        #pragma unroll
        for (int j = 0; j < 8; j++) {
            float t = acc[i][j]*sc + bs;
            if (ADD) t += Sb[(size_t)row*Nc + bn0 + rn + j];
            v[j] = rl ? fmaxf(t, 0.f) : t;
        }
        *(float4*)(Cb + (size_t)row*Nc + bn0 + rn)     = make_float4(v[0],v[1],v[2],v[3]);
        *(float4*)(Cb + (size_t)row*Nc + bn0 + rn + 4) = make_float4(v[4],v[5],v[6],v[7]);
    }
}

// ---------------- transpose (B,192,2048) -> (B,2048,192) ----------------
__global__ void transpose192(const float* __restrict__ src, float* __restrict__ dst)
{
    __shared__ float tile[32][33];
    int b = blockIdx.z;
    int n0 = blockIdx.x*32, c0 = blockIdx.y*32;
    const float* s = src + (size_t)b*192*NN;
    float* d = dst + (size_t)b*NN*192;
    for (int i = threadIdx.y; i < 32; i += 8)
        tile[i][threadIdx.x] = s[(size_t)(c0+i)*NN + n0 + threadIdx.x];
    __syncthreads();
    for (int i = threadIdx.y; i < 32; i += 8)
        d[(size_t)(n0+i)*192 + c0 + threadIdx.x] = tile[threadIdx.x][i];
}

// ---------------- fused rel_xyz + fd1 (K=3 conv + folded BN + relu) ----------------
__global__ void posenc1(const float* __restrict__ xyz, const float* __restrict__ fd1_w)
{
    __shared__ float srel[3][32];
    int b = blockIdx.y;
    int base = blockIdx.x * 32;
    int tid = threadIdx.x;
    if (tid < 32) {
        int col = base + tid;
        int n = col >> 4, j = col & 15;
        int id = g_idx[b*KK*NN + j*NN + n];
        const float* xb = xyz + b*3*NN;
        srel[0][tid] = xb[n]      - xb[id];
        srel[1][tid] = xb[NN+n]   - xb[NN+id];
        srel[2][tid] = xb[2*NN+n] - xb[2*NN+id];
    }
    __syncthreads();
    int lane = tid & 31, w = tid >> 5;
    float rx = srel[0][lane], ry = srel[1][lane], rz = srel[2][lane];
    #pragma unroll
    for (int it = 0; it < 8; ++it) {
        int m = it*8 + w;
        float v = fd1_w[m*3]*rx + fd1_w[m*3+1]*ry + fd1_w[m*3+2]*rz;
        v = fmaxf(v * g_fold[m] + g_fold[64+m], 0.f);
        g_t1[(size_t)(b*64+m)*NK + base + lane] = v;
    }
}

// ---------------- G = q - k_gather + pos ; Vrel = v_gather + pos ----------------
__global__ void gv_build()
{
    int t = blockIdx.x*blockDim.x + threadIdx.x;
    if (t >= BB*NN*KK) return;
    int j = t & 15; int n = (t >> 4) & 2047; int b = t >> 15;
    int id = g_idx[b*KK*NN + j*NN + n];
    const float* qt = g_qkvt + ((size_t)b*NN + n )*192;
    const float* kt = g_qkvt + ((size_t)b*NN + id)*192 + 64;
    const float* vt = kt + 64;
    #pragma unroll 4
    for (int c = 0; c < DD; c++) {
        size_t off = ((size_t)(b*DD + c)*NN + n)*KK + j;
        float p = g_pos[off];
        g_G[off]  = qt[c] - kt[c] + p;
        g_vr[off] = vt[c] + p;
    }
}

// ---------------- fused ConvTranspose(4,1) + softmax(c) + weighted sum + identity ----------------
__global__ void __launch_bounds__(256) k4_kernel(const float* __restrict__ at_b,
                                                 float* __restrict__ res_out)
{
    __shared__ float s_a[64*16];
    __shared__ float s_v[16*64];
    __shared__ float s_m[16][8];
    __shared__ float s_s[16][8];
    __shared__ float s_out[256];
    int bn = blockIdx.x;
    int b = bn >> 11, n = bn & 2047;
    int tid = threadIdx.x;
    int o = tid & 63, r = tid >> 6;
    int lane = tid & 31, warp = tid >> 5;
    {
        int c = tid >> 2, fq = (tid & 3) * 4;
        size_t base = ((size_t)(b*64 + c)*2048 + n)*16 + fq;
        float4 a4 = *(const float4*)(g_at + base);
        *(float4*)(s_a + c*16 + fq) = a4;
        float4 v4 = *(const float4*)(g_vr + base);
        s_v[(fq+0)*64 + c] = v4.x;
        s_v[(fq+1)*64 + c] = v4.y;
        s_v[(fq+2)*64 + c] = v4.z;
        s_v[(fq+3)*64 + c] = v4.w;
    }
    __syncthreads();

    float y[16];
    float bo = at_b[o];
    #pragma unroll
    for (int f = 0; f < 16; f++) y[f] = bo;
    const float* w = g_wT + r*4096 + o;
    #pragma unroll 4
    for (int c = 0; c < 64; c++) {
        float wv = w[c*64];
        const float4* ap = (const float4*)(s_a + c*16);
        float4 a0 = ap[0], a1 = ap[1], a2 = ap[2], a3 = ap[3];
        y[0]  = fmaf(wv, a0.x, y[0]);  y[1]  = fmaf(wv, a0.y, y[1]);
        y[2]  = fmaf(wv, a0.z, y[2]);  y[3]  = fmaf(wv, a0.w, y[3]);
        y[4]  = fmaf(wv, a1.x, y[4]);  y[5]  = fmaf(wv, a1.y, y[5]);
        y[6]  = fmaf(wv, a1.z, y[6]);  y[7]  = fmaf(wv, a1.w, y[7]);
        y[8]  = fmaf(wv, a2.x, y[8]);  y[9]  = fmaf(wv, a2.y, y[9]);
        y[10] = fmaf(wv, a2.z, y[10]); y[11] = fmaf(wv, a2.w, y[11]);
        y[12] = fmaf(wv, a3.x, y[12]); y[13] = fmaf(wv, a3.y, y[13]);
        y[14] = fmaf(wv, a3.z, y[14]); y[15] = fmaf(wv, a3.w, y[15]);
    }
    #pragma unroll
    for (int f = 0; f < 16; f++) {
        float m = y[f];
        #pragma unroll
        for (int off = 16; off; off >>= 1) m = fmaxf(m, __shfl_xor_sync(0xffffffffu, m, off));
        if (lane == 0) s_m[f][warp] = m;
    }
    __syncthreads();
    #pragma unroll
    for (int f = 0; f < 16; f++) {
        float m = fmaxf(s_m[f][2*r], s_m[f][2*r+1]);
        float e = __expf(y[f] - m);
        y[f] = e;
        float sm = e;
        #pragma unroll
        for (int off = 16; off; off >>= 1) sm += __shfl_xor_sync(0xffffffffu, sm, off);
        if (lane == 0) s_s[f][warp] = sm;
    }
    __syncthreads();
    float acc = 0.f;
    #pragma unroll
    for (int f = 0; f < 16; f++) {
        float sum = s_s[f][2*r] + s_s[f][2*r+1];
        acc = fmaf(y[f] / sum, s_v[f*64 + o], acc);
    }
    acc += g_x[(size_t)b*131072 + o*2048 + n];
    s_out[o*4 + r] = acc;
    __syncthreads();
    if (tid < 64) {
        float4 ov = *(const float4*)(s_out + tid*4);
        *(float4*)(res_out + (size_t)b*524288 + (size_t)tid*8192 + n*4) = ov;
    }
}

// ---------------- m42: (3x64) @ ch, memory-bound ----------------
__global__ void m42k(const float* __restrict__ w, const float* __restrict__ bias,
                     float* __restrict__ out)
{
    int t = blockIdx.x*blockDim.x + threadIdx.x;
    int col = t & 8191, b = t >> 13;
    float a0 = bias[0], a1 = bias[1], a2 = bias[2];
    const float* ch = g_ch + (size_t)b*524288 + col;
    #pragma unroll 8
    for (int c = 0; c < 64; c++) {
        float xv = ch[(size_t)c*8192];
        a0 = fmaf(w[c], xv, a0);
        a1 = fmaf(w[64+c], xv, a1);
        a2 = fmaf(w[128+c], xv, a2);
    }
    out[(size_t)(b*3+0)*8192 + col] = a0;
    out[(size_t)(b*3+1)*8192 + col] = a1;
    out[(size_t)(b*3+2)*8192 + col] = a2;
}

// ---------------- launch ----------------
extern "C" void kernel_launch(void* const* d_in, const int* in_sizes, int n_in,
                              void* d_out, int out_size)
{
    const float* feature = (const float*)d_in[0];
    const float* xyz     = (const float*)d_in[1];
    const float* bt1_w = (const float*)d_in[2];  const float* bt1_b = (const float*)d_in[3];
    const float* bt2_w = (const float*)d_in[4];  const float* bt2_b = (const float*)d_in[5];
    const float* bts_w = (const float*)d_in[6];  const float* bts_b = (const float*)d_in[7];
    const float* q_w   = (const float*)d_in[8];  const float* q_b   = (const float*)d_in[9];
    const float* k_w   = (const float*)d_in[10]; const float* k_b   = (const float*)d_in[11];
    const float* v_w   = (const float*)d_in[12]; const float* v_b   = (const float*)d_in[13];
    const float* fd1_w = (const float*)d_in[14]; const float* fd1_b = (const float*)d_in[15];
    const float* fd_g  = (const float*)d_in[16]; const float* fd_bb = (const float*)d_in[17];
    const float* fd2_w = (const float*)d_in[18]; const float* fd2_b = (const float*)d_in[19];
    const float* fg1_w = (const float*)d_in[20]; const float* fg1_b = (const float*)d_in[21];
    const float* fg_g  = (const float*)d_in[22]; const float* fg_bb = (const float*)d_in[23];
    const float* fg2_w = (const float*)d_in[24]; const float* fg2_b = (const float*)d_in[25];
    const float* at_w  = (const float*)d_in[26]; const float* at_b  = (const float*)d_in[27];
    const float* m41_w = (const float*)d_in[28]; const float* m41_b = (const float*)d_in[29];
    const float* m42_w = (const float*)d_in[30]; const float* m42_b = (const float*)d_in[31];

    float *phx, *px, *pqkv, *pqkvt, *pt1, *ppos, *pG, *pH, *pat, *pch, *pfold;
    float *pwbt1s, *pbbt1s, *pwbt2, *pwqkv, *pbqkv, *pwfd2, *pwfg1, *pwfg2, *pwm41, *pvr;
    cudaGetSymbolAddress((void**)&phx,   g_hx);
    cudaGetSymbolAddress((void**)&px,    g_x);
    cudaGetSymbolAddress((void**)&pqkv,  g_qkv);
    cudaGetSymbolAddress((void**)&pqkvt, g_qkvt);
    cudaGetSymbolAddress((void**)&pt1,   g_t1);
    cudaGetSymbolAddress((void**)&ppos,  g_pos);
    cudaGetSymbolAddress((void**)&pG,    g_G);
    cudaGetSymbolAddress((void**)&pvr,   g_vr);
    cudaGetSymbolAddress((void**)&pH,    g_H);
    cudaGetSymbolAddress((void**)&pat,   g_at);
    cudaGetSymbolAddress((void**)&pch,   g_ch);
    cudaGetSymbolAddress((void**)&pfold, g_fold);
    cudaGetSymbolAddress((void**)&pwbt1s,g_w_bt1s);
    cudaGetSymbolAddress((void**)&pbbt1s,g_b_bt1s);
    cudaGetSymbolAddress((void**)&pwbt2, g_w_bt2);
    cudaGetSymbolAddress((void**)&pwqkv, g_w_qkv);
    cudaGetSymbolAddress((void**)&pbqkv, g_b_qkv);
    cudaGetSymbolAddress((void**)&pwfd2, g_w_fd2);
    cudaGetSymbolAddress((void**)&pwfg1, g_w_fg1);
    cudaGetSymbolAddress((void**)&pwfg2, g_w_fg2);
    cudaGetSymbolAddress((void**)&pwm41, g_w_m41);

    float* out = (float*)d_out;
    float* res = out + BB*3*4*NN;

    prep_kernel<<<256, 256>>>(fd_g, fd1_b, fd_bb, fg_g, fg1_b, fg_bb, at_w,
                              bt1_w, bt1_b, bts_w, bts_b, bt2_w,
                              q_w, q_b, k_w, k_b, v_w, v_b,
                              fd2_w, fg1_w, fg2_w, m41_w);
    knn_kernel<<<BB*NN/16, 512>>>(xyz);

    // stacked bt1(relu)+bts -> g_hx [B][128][2048]
    gemmT<128,64,false,false><<<dim3(32,1,BB),128>>>(pwbt1s, 128, feature, (size_t)480*NN,
        nullptr, pbbt1s, nullptr, 0, phx, (size_t)128*NN, 480, NN, 64);
    // bt2 @ h + bt2_b + xs -> g_x
    gemmT<64,128,true,false><<<dim3(16,1,BB),128>>>(pwbt2, 64, phx, (size_t)128*NN,
        nullptr, bt2_b, phx + 64*NN, (size_t)128*NN, px, (size_t)64*NN, 64, NN, 0);
    // stacked qkv -> g_qkv [B][192][2048]
    gemmT<64,128,false,false><<<dim3(16,3,BB),128>>>(pwqkv, 192, px, (size_t)64*NN,
        nullptr, pbqkv, nullptr, 0, pqkv, (size_t)192*NN, 64, NN, 0);
    transpose192<<<dim3(64,6,BB), dim3(32,8)>>>(pqkv, pqkvt);

    // pos_enc
    posenc1<<<dim3(NK/32, BB), 256>>>(xyz, fd1_w);
    gemmT<64,128,false,false><<<dim3(256,1,BB),128>>>(pwfd2, 64, pt1, (size_t)64*NK,
        nullptr, fd2_b, nullptr, 0, ppos, (size_t)64*NK, 64, NK, 0);

    // attention MLP
    gv_build<<<512, 256>>>();
    gemmT<128,128,false,true><<<dim3(256,2,BB),256>>>(pwfg1, 256, pG, (size_t)64*NK,
        pfold+128, pfold+384, nullptr, 0, pH, (size_t)256*NK, 64, NK, 256);
    gemmT<64,128,false,false><<<dim3(256,1,BB),128>>>(pwfg2, 64, pH, (size_t)256*NK,
        nullptr, fg2_b, nullptr, 0, pat, (size_t)64*NK, 256, NK, 0);

    // fused upsample-attention + identity -> res
    k4_kernel<<<BB*NN, 256>>>(at_b, res);

    // completion head
    gemmT<64,128,false,false><<<dim3(64,1,BB),128>>>(pwm41, 64, res, (size_t)64*4*NN,
        nullptr, m41_b, nullptr, 0, pch, (size_t)64*4*NN, 64, 4*NN, 64);
    m42k<<<BB*4*NN/256, 256>>>(m42_w, m42_b, out);
}

// round 3
// speedup vs baseline: 1.2708x; 1.0008x over previous
#include <cuda_runtime.h>
#include <cstdint>

#define BB 4
#define NN 2048
#define KK 16
#define DD 64
#define NK (NN*KK)
#define EPSV 1e-5f

// ---------------- scratch (device globals) ----------------
__device__ float g_hx  [BB*128*NN];          // stacked [h(0:64); xs(64:128)]
__device__ float g_x   [BB*DD*NN];
__device__ float g_qkv [BB*192*NN];          // [b][192][n]
__device__ float g_qkvt[BB*NN*192];          // [b][n][192] (q,k,v)
__device__ int   g_idx [BB*KK*NN];
__device__ float g_t1  [BB*DD*NK];
__device__ float g_pos [BB*DD*NK];
__device__ float g_G   [BB*DD*NK];
__device__ float g_vr  [BB*DD*NK];
__device__ float g_H   [(size_t)BB*256*NK];
__device__ float g_at  [BB*DD*NK];
__device__ float g_ch  [BB*DD*4*NN];
__device__ float g_fold[640];                // [0:64) s_fd [64:128) b_fd [128:384) s_fg [384:640) b_fg
__device__ float g_wT  [4*64*64];            // at_w -> [r][c][o]
// pre-transposed weights [K][M]
__device__ float g_w_bt1s[480*128];
__device__ float g_b_bt1s[128];
__device__ float g_w_bt2 [64*64];
__device__ float g_w_qkv [64*192];
__device__ float g_b_qkv [192];
__device__ float g_w_fd2 [64*64];
__device__ float g_w_fg1 [64*256];
__device__ float g_w_fg2 [256*64];
__device__ float g_w_m41 [64*64];

// ---------------- prep: fold BN, transpose all weights ----------------
__global__ void prep_kernel(const float* __restrict__ fd_g, const float* __restrict__ fd1_b,
                            const float* __restrict__ fd_bb,
                            const float* __restrict__ fg_g, const float* __restrict__ fg1_b,
                            const float* __restrict__ fg_bb,
                            const float* __restrict__ at_w,
                            const float* __restrict__ bt1_w, const float* __restrict__ bt1_b,
                            const float* __restrict__ bts_w, const float* __restrict__ bts_b,
                            const float* __restrict__ bt2_w,
                            const float* __restrict__ q_w, const float* __restrict__ q_b,
                            const float* __restrict__ k_w, const float* __restrict__ k_b,
                            const float* __restrict__ v_w, const float* __restrict__ v_b,
                            const float* __restrict__ fd2_w,
                            const float* __restrict__ fg1_w, const float* __restrict__ fg2_w,
                            const float* __restrict__ m41_w)
{
    int t = blockIdx.x * blockDim.x + threadIdx.x;
    float inv = rsqrtf(1.f + EPSV);
    if (t < 64)  { float s = fd_g[t]*inv; g_fold[t] = s;     g_fold[64+t]  = fd1_b[t]*s + fd_bb[t]; }
    if (t < 256) { float s = fg_g[t]*inv; g_fold[128+t] = s; g_fold[384+t] = fg1_b[t]*s + fg_bb[t]; }
    if (t < 16384) {
        int r = t & 3, o = (t >> 2) & 63, c = t >> 8;
        g_wT[r*4096 + c*64 + o] = at_w[t];                   // at_w[c][o][r]
        { int k = t >> 8, m = t & 255; g_w_fg1[k*256 + m] = fg1_w[m*64 + k]; }
        { int k = t >> 6, m = t & 63;  g_w_fg2[k*64 + m]  = fg2_w[m*256 + k]; }
    }
    if (t < 61440) { int k = t >> 7, m = t & 127;
        g_w_bt1s[t] = (m < 64) ? bt1_w[m*480 + k] : bts_w[(m-64)*480 + k]; }
    if (t < 128) g_b_bt1s[t] = (t < 64) ? bt1_b[t] : bts_b[t-64];
    if (t < 12288) { int k = t / 192, m = t % 192;
        g_w_qkv[t] = (m < 64) ? q_w[m*64+k] : (m < 128 ? k_w[(m-64)*64+k] : v_w[(m-128)*64+k]); }
    if (t < 192) g_b_qkv[t] = (t < 64) ? q_b[t] : (t < 128 ? k_b[t-64] : v_b[t-128]);
    if (t < 4096) { int k = t >> 6, m = t & 63;
        g_w_bt2[t] = bt2_w[m*64+k];
        g_w_fd2[t] = fd2_w[m*64+k];
        g_w_m41[t] = m41_w[m*64+k]; }
}

// ---------------- KNN: warp per point ----------------
__global__ void knn_kernel(const float* __restrict__ xyz)
{
    __shared__ float sx[NN], sy[NN], sz[NN], ssq[NN];
    int b  = blockIdx.x >> 7;
    int n0 = (blockIdx.x & 127) * 16;
    const float* xb = xyz + b*3*NN;
    for (int m = threadIdx.x; m < NN; m += blockDim.x) {
        float px = xb[m], py = xb[NN+m], pz = xb[2*NN+m];
        sx[m]=px; sy[m]=py; sz[m]=pz; ssq[m] = px*px + py*py + pz*pz;
    }
    __syncthreads();
    int warp = threadIdx.x >> 5, lane = threadIdx.x & 31;
    int n = n0 + warp;
    float px = sx[n], py = sy[n], pz = sz[n], sqn = ssq[n];

    float bv[17]; int bi[17];
    #pragma unroll
    for (int i = 0; i < 17; i++) { bv[i] = 3.4e38f; bi[i] = 0x7fffffff; }
    for (int m = lane; m < NN; m += 32) {
        float d2 = sqn + ssq[m] - 2.f*(px*sx[m] + py*sy[m] + pz*sz[m]);
        if (d2 < bv[16]) {
            bv[16] = d2; bi[16] = m;
            #pragma unroll
            for (int s = 16; s > 0; --s)
                if (bv[s] < bv[s-1]) {
                    float tv = bv[s]; bv[s] = bv[s-1]; bv[s-1] = tv;
                    int   ti = bi[s]; bi[s] = bi[s-1]; bi[s-1] = ti;
                }
        }
    }
    for (int t = 0; t < 17; ++t) {
        float hv = bv[0]; int hi = bi[0];
        float v = hv; int id = hi;
        #pragma unroll
        for (int off = 16; off; off >>= 1) {
            float ov = __shfl_xor_sync(0xffffffffu, v, off);
            int   oi = __shfl_xor_sync(0xffffffffu, id, off);
            if (ov < v || (ov == v && oi < id)) { v = ov; id = oi; }
        }
        if (t > 0 && lane == 0) g_idx[b*KK*NN + (t-1)*NN + n] = id;
        if (hv == v && hi == id) {
            #pragma unroll
            for (int s = 0; s < 16; ++s) { bv[s] = bv[s+1]; bi[s] = bi[s+1]; }
            bv[16] = 3.4e38f; bi[16] = 0x7fffffff;
        }
    }
}

// ---------------- tiled fp32 GEMM, Wt pre-transposed [K][M], 8x8 reg tiles ----------------
template<int BM, int BN, bool ADD, bool SCALE>
__global__ void __launch_bounds__((BM/8)*(BN/8))
gemmT(const float* __restrict__ Wt, int ldw,
      const float* __restrict__ X, size_t xbs,
      const float* __restrict__ scale, const float* __restrict__ bias,
      const float* __restrict__ S, size_t sbs,
      float* __restrict__ C, size_t cbs,
      int Kd, int Nc, int relu_rows)
{
    constexpr int KC = 8;
    constexpr int NTH = (BM/8)*(BN/8);
    constexpr int W4 = KC*BM/4, X4 = KC*BN/4;
    constexpr int WPT = (W4 + NTH - 1)/NTH, XPT = (X4 + NTH - 1)/NTH;
    __shared__ __align__(16) float sW[2][KC][BM];
    __shared__ __align__(16) float sX[2][KC][BN];
    int tid = threadIdx.x;
    int bn0 = blockIdx.x * BN;
    int bm0 = blockIdx.y * BM;
    const float* Xb = X + (size_t)blockIdx.z * xbs;
    const float* Sb = S ? S + (size_t)blockIdx.z * sbs : nullptr;
    float* Cb = C + (size_t)blockIdx.z * cbs;

    float4 wr[WPT], xr[XPT];
    float acc[8][8] = {};
    int tx = tid % (BN/8), ty = tid / (BN/8);
    int rm = ty*8, rn = tx*8;
    int nch = Kd / KC;

    // fetch chunk 0
    {
        #pragma unroll
        for (int i = 0; i < WPT; i++) { int t = tid + i*NTH; if (t < W4) {
            int k = t/(BM/4), m4 = t%(BM/4);
            wr[i] = *(const float4*)(Wt + (size_t)k*ldw + bm0 + m4*4); } }
        #pragma unroll
        for (int i = 0; i < XPT; i++) { int t = tid + i*NTH; if (t < X4) {
            int k = t/(BN/4), n4 = t%(BN/4);
            xr[i] = *(const float4*)(Xb + (size_t)k*Nc + bn0 + n4*4); } }
        #pragma unroll
        for (int i = 0; i < WPT; i++) { int t = tid + i*NTH; if (t < W4) {
            int k = t/(BM/4), m4 = t%(BM/4); *(float4*)&sW[0][k][m4*4] = wr[i]; } }
        #pragma unroll
        for (int i = 0; i < XPT; i++) { int t = tid + i*NTH; if (t < X4) {
            int k = t/(BN/4), n4 = t%(BN/4); *(float4*)&sX[0][k][n4*4] = xr[i]; } }
    }
    __syncthreads();

    for (int c = 0; c < nch; ++c) {
        if (c + 1 < nch) {
            int k0 = (c+1)*KC;
            #pragma unroll
            for (int i = 0; i < WPT; i++) { int t = tid + i*NTH; if (t < W4) {
                int k = t/(BM/4), m4 = t%(BM/4);
                wr[i] = *(const float4*)(Wt + (size_t)(k0+k)*ldw + bm0 + m4*4); } }
            #pragma unroll
            for (int i = 0; i < XPT; i++) { int t = tid + i*NTH; if (t < X4) {
                int k = t/(BN/4), n4 = t%(BN/4);
                xr[i] = *(const float4*)(Xb + (size_t)(k0+k)*Nc + bn0 + n4*4); } }
        }
        int buf = c & 1;
        #pragma unroll
        for (int k = 0; k < KC; ++k) {
            float4 a0 = *(const float4*)&sW[buf][k][rm];
            float4 a1 = *(const float4*)&sW[buf][k][rm+4];
            float4 b0 = *(const float4*)&sX[buf][k][rn];
            float4 b1 = *(const float4*)&sX[buf][k][rn+4];
            float a[8] = {a0.x,a0.y,a0.z,a0.w,a1.x,a1.y,a1.z,a1.w};
            float bb[8] = {b0.x,b0.y,b0.z,b0.w,b1.x,b1.y,b1.z,b1.w};
            #pragma unroll
            for (int i = 0; i < 8; i++)
                #pragma unroll
                for (int j = 0; j < 8; j++) acc[i][j] = fmaf(a[i], bb[j], acc[i][j]);
        }
        if (c + 1 < nch) {
            int nb = (c+1) & 1;
            #pragma unroll
            for (int i = 0; i < WPT; i++) { int t = tid + i*NTH; if (t < W4) {
                int k = t/(BM/4), m4 = t%(BM/4); *(float4*)&sW[nb][k][m4*4] = wr[i]; } }
            #pragma unroll
            for (int i = 0; i < XPT; i++) { int t = tid + i*NTH; if (t < X4) {
                int k = t/(BN/4), n4 = t%(BN/4); *(float4*)&sX[nb][k][n4*4] = xr[i]; } }
        }
        __syncthreads();
    }

    #pragma unroll
    for (int i = 0; i < 8; i++) {
        int row = bm0 + rm + i;
        float sc = SCALE ? scale[row] : 1.f;
        float bs = bias[row];
        bool rl = row < relu_rows;
        float v[8];
        #pragma unroll
        for (int j = 0; j < 8; j++) {
            float t = acc[i][j]*sc + bs;
            if (ADD) t += Sb[(size_t)row*Nc + bn0 + rn + j];
            v[j] = rl ? fmaxf(t, 0.f) : t;
        }
        *(float4*)(Cb + (size_t)row*Nc + bn0 + rn)     = make_float4(v[0],v[1],v[2],v[3]);
        *(float4*)(Cb + (size_t)row*Nc + bn0 + rn + 4) = make_float4(v[4],v[5],v[6],v[7]);
    }
}

// ---------------- transpose (B,192,2048) -> (B,2048,192) ----------------
__global__ void transpose192(const float* __restrict__ src, float* __restrict__ dst)
{
    __shared__ float tile[32][33];
    int b = blockIdx.z;
    int n0 = blockIdx.x*32, c0 = blockIdx.y*32;
    const float* s = src + (size_t)b*192*NN;
    float* d = dst + (size_t)b*NN*192;
    for (int i = threadIdx.y; i < 32; i += 8)
        tile[i][threadIdx.x] = s[(size_t)(c0+i)*NN + n0 + threadIdx.x];
    __syncthreads();
    for (int i = threadIdx.y; i < 32; i += 8)
        d[(size_t)(n0+i)*192 + c0 + threadIdx.x] = tile[threadIdx.x][i];
}

// ---------------- fused rel_xyz + fd1 (K=3 conv + folded BN + relu) ----------------
__global__ void posenc1(const float* __restrict__ xyz, const float* __restrict__ fd1_w)
{
    __shared__ float srel[3][32];
    int b = blockIdx.y;
    int base = blockIdx.x * 32;
    int tid = threadIdx.x;
    if (tid < 32) {
        int col = base + tid;
        int n = col >> 4, j = col & 15;
        int id = g_idx[b*KK*NN + j*NN + n];
        const float* xb = xyz + b*3*NN;
        srel[0][tid] = xb[n]      - xb[id];
        srel[1][tid] = xb[NN+n]   - xb[NN+id];
        srel[2][tid] = xb[2*NN+n] - xb[2*NN+id];
    }
    __syncthreads();
    int lane = tid & 31, w = tid >> 5;
    float rx = srel[0][lane], ry = srel[1][lane], rz = srel[2][lane];
    #pragma unroll
    for (int it = 0; it < 8; ++it) {
        int m = it*8 + w;
        float v = fd1_w[m*3]*rx + fd1_w[m*3+1]*ry + fd1_w[m*3+2]*rz;
        v = fmaxf(v * g_fold[m] + g_fold[64+m], 0.f);
        g_t1[(size_t)(b*64+m)*NK + base + lane] = v;
    }
}

// ---------------- G = q - k_gather + pos ; Vrel = v_gather + pos ----------------
__global__ void gv_build()
{
    int t = blockIdx.x*blockDim.x + threadIdx.x;
    if (t >= BB*NN*KK) return;
    int j = t & 15; int n = (t >> 4) & 2047; int b = t >> 15;
    int id = g_idx[b*KK*NN + j*NN + n];
    const float* qt = g_qkvt + ((size_t)b*NN + n )*192;
    const float* kt = g_qkvt + ((size_t)b*NN + id)*192 + 64;
    const float* vt = kt + 64;
    #pragma unroll 4
    for (int c = 0; c < DD; c++) {
        size_t off = ((size_t)(b*DD + c)*NN + n)*KK + j;
        float p = g_pos[off];
        g_G[off]  = qt[c] - kt[c] + p;
        g_vr[off] = vt[c] + p;
    }
}

// ---------------- fused ConvTranspose(4,1) + softmax(c) + weighted sum + identity ----------------
__global__ void __launch_bounds__(256) k4_kernel(const float* __restrict__ at_b,
                                                 float* __restrict__ res_out)
{
    __shared__ float s_a[64*16];
    __shared__ float s_v[16*64];
    __shared__ float s_m[16][8];
    __shared__ float s_s[16][8];
    __shared__ float s_out[256];
    int bn = blockIdx.x;
    int b = bn >> 11, n = bn & 2047;
    int tid = threadIdx.x;
    int o = tid & 63, r = tid >> 6;
    int lane = tid & 31, warp = tid >> 5;
    {
        int c = tid >> 2, fq = (tid & 3) * 4;
        size_t base = ((size_t)(b*64 + c)*2048 + n)*16 + fq;
        float4 a4 = *(const float4*)(g_at + base);
        *(float4*)(s_a + c*16 + fq) = a4;
        float4 v4 = *(const float4*)(g_vr + base);
        s_v[(fq+0)*64 + c] = v4.x;
        s_v[(fq+1)*64 + c] = v4.y;
        s_v[(fq+2)*64 + c] = v4.z;
        s_v[(fq+3)*64 + c] = v4.w;
    }
    __syncthreads();

    float y[16];
    float bo = at_b[o];
    #pragma unroll
    for (int f = 0; f < 16; f++) y[f] = bo;
    const float* w = g_wT + r*4096 + o;
    #pragma unroll 4
    for (int c = 0; c < 64; c++) {
        float wv = w[c*64];
        const float4* ap = (const float4*)(s_a + c*16);
        float4 a0 = ap[0], a1 = ap[1], a2 = ap[2], a3 = ap[3];
        y[0]  = fmaf(wv, a0.x, y[0]);  y[1]  = fmaf(wv, a0.y, y[1]);
        y[2]  = fmaf(wv, a0.z, y[2]);  y[3]  = fmaf(wv, a0.w, y[3]);
        y[4]  = fmaf(wv, a1.x, y[4]);  y[5]  = fmaf(wv, a1.y, y[5]);
        y[6]  = fmaf(wv, a1.z, y[6]);  y[7]  = fmaf(wv, a1.w, y[7]);
        y[8]  = fmaf(wv, a2.x, y[8]);  y[9]  = fmaf(wv, a2.y, y[9]);
        y[10] = fmaf(wv, a2.z, y[10]); y[11] = fmaf(wv, a2.w, y[11]);
        y[12] = fmaf(wv, a3.x, y[12]); y[13] = fmaf(wv, a3.y, y[13]);
        y[14] = fmaf(wv, a3.z, y[14]); y[15] = fmaf(wv, a3.w, y[15]);
    }
    #pragma unroll
    for (int f = 0; f < 16; f++) {
        float m = y[f];
        #pragma unroll
        for (int off = 16; off; off >>= 1) m = fmaxf(m, __shfl_xor_sync(0xffffffffu, m, off));
        if (lane == 0) s_m[f][warp] = m;
    }
    __syncthreads();
    #pragma unroll
    for (int f = 0; f < 16; f++) {
        float m = fmaxf(s_m[f][2*r], s_m[f][2*r+1]);
        float e = __expf(y[f] - m);
        y[f] = e;
        float sm = e;
        #pragma unroll
        for (int off = 16; off; off >>= 1) sm += __shfl_xor_sync(0xffffffffu, sm, off);
        if (lane == 0) s_s[f][warp] = sm;
    }
    __syncthreads();
    float acc = 0.f;
    #pragma unroll
    for (int f = 0; f < 16; f++) {
        float sum = s_s[f][2*r] + s_s[f][2*r+1];
        acc = fmaf(y[f] / sum, s_v[f*64 + o], acc);
    }
    acc += g_x[(size_t)b*131072 + o*2048 + n];
    s_out[o*4 + r] = acc;
    __syncthreads();
    if (tid < 64) {
        float4 ov = *(const float4*)(s_out + tid*4);
        *(float4*)(res_out + (size_t)b*524288 + (size_t)tid*8192 + n*4) = ov;
    }
}

// ---------------- m42: (3x64) @ ch, memory-bound ----------------
__global__ void m42k(const float* __restrict__ w, const float* __restrict__ bias,
                     float* __restrict__ out)
{
    int t = blockIdx.x*blockDim.x + threadIdx.x;
    int col = t & 8191, b = t >> 13;
    float a0 = bias[0], a1 = bias[1], a2 = bias[2];
    const float* ch = g_ch + (size_t)b*524288 + col;
    #pragma unroll 8
    for (int c = 0; c < 64; c++) {
        float xv = ch[(size_t)c*8192];
        a0 = fmaf(w[c], xv, a0);
        a1 = fmaf(w[64+c], xv, a1);
        a2 = fmaf(w[128+c], xv, a2);
    }
    out[(size_t)(b*3+0)*8192 + col] = a0;
    out[(size_t)(b*3+1)*8192 + col] = a1;
    out[(size_t)(b*3+2)*8192 + col] = a2;
}

// ---------------- launch ----------------
extern "C" void kernel_launch(void* const* d_in, const int* in_sizes, int n_in,
                              void* d_out, int out_size)
{
    const float* feature = (const float*)d_in[0];
    const float* xyz     = (const float*)d_in[1];
    const float* bt1_w = (const float*)d_in[2];  const float* bt1_b = (const float*)d_in[3];
    const float* bt2_w = (const float*)d_in[4];  const float* bt2_b = (const float*)d_in[5];
    const float* bts_w = (const float*)d_in[6];  const float* bts_b = (const float*)d_in[7];
    const float* q_w   = (const float*)d_in[8];  const float* q_b   = (const float*)d_in[9];
    const float* k_w   = (const float*)d_in[10]; const float* k_b   = (const float*)d_in[11];
    const float* v_w   = (const float*)d_in[12]; const float* v_b   = (const float*)d_in[13];
    const float* fd1_w = (const float*)d_in[14]; const float* fd1_b = (const float*)d_in[15];
    const float* fd_g  = (const float*)d_in[16]; const float* fd_bb = (const float*)d_in[17];
    const float* fd2_w = (const float*)d_in[18]; const float* fd2_b = (const float*)d_in[19];
    const float* fg1_w = (const float*)d_in[20]; const float* fg1_b = (const float*)d_in[21];
    const float* fg_g  = (const float*)d_in[22]; const float* fg_bb = (const float*)d_in[23];
    const float* fg2_w = (const float*)d_in[24]; const float* fg2_b = (const float*)d_in[25];
    const float* at_w  = (const float*)d_in[26]; const float* at_b  = (const float*)d_in[27];
    const float* m41_w = (const float*)d_in[28]; const float* m41_b = (const float*)d_in[29];
    const float* m42_w = (const float*)d_in[30]; const float* m42_b = (const float*)d_in[31];

    float *phx, *px, *pqkv, *pqkvt, *pt1, *ppos, *pG, *pH, *pat, *pch, *pfold;
    float *pwbt1s, *pbbt1s, *pwbt2, *pwqkv, *pbqkv, *pwfd2, *pwfg1, *pwfg2, *pwm41, *pvr;
    cudaGetSymbolAddress((void**)&phx,   g_hx);
    cudaGetSymbolAddress((void**)&px,    g_x);
    cudaGetSymbolAddress((void**)&pqkv,  g_qkv);
    cudaGetSymbolAddress((void**)&pqkvt, g_qkvt);
    cudaGetSymbolAddress((void**)&pt1,   g_t1);
    cudaGetSymbolAddress((void**)&ppos,  g_pos);
    cudaGetSymbolAddress((void**)&pG,    g_G);
    cudaGetSymbolAddress((void**)&pvr,   g_vr);
    cudaGetSymbolAddress((void**)&pH,    g_H);
    cudaGetSymbolAddress((void**)&pat,   g_at);
    cudaGetSymbolAddress((void**)&pch,   g_ch);
    cudaGetSymbolAddress((void**)&pfold, g_fold);
    cudaGetSymbolAddress((void**)&pwbt1s,g_w_bt1s);
    cudaGetSymbolAddress((void**)&pbbt1s,g_b_bt1s);
    cudaGetSymbolAddress((void**)&pwbt2, g_w_bt2);
    cudaGetSymbolAddress((void**)&pwqkv, g_w_qkv);
    cudaGetSymbolAddress((void**)&pbqkv, g_b_qkv);
    cudaGetSymbolAddress((void**)&pwfd2, g_w_fd2);
    cudaGetSymbolAddress((void**)&pwfg1, g_w_fg1);
    cudaGetSymbolAddress((void**)&pwfg2, g_w_fg2);
    cudaGetSymbolAddress((void**)&pwm41, g_w_m41);

    float* out = (float*)d_out;
    float* res = out + BB*3*4*NN;

    prep_kernel<<<256, 256>>>(fd_g, fd1_b, fd_bb, fg_g, fg1_b, fg_bb, at_w,
                              bt1_w, bt1_b, bts_w, bts_b, bt2_w,
                              q_w, q_b, k_w, k_b, v_w, v_b,
                              fd2_w, fg1_w, fg2_w, m41_w);
    knn_kernel<<<BB*NN/16, 512>>>(xyz);

    // stacked bt1(relu)+bts -> g_hx [B][128][2048]
    gemmT<128,64,false,false><<<dim3(32,1,BB),128>>>(pwbt1s, 128, feature, (size_t)480*NN,
        nullptr, pbbt1s, nullptr, 0, phx, (size_t)128*NN, 480, NN, 64);
    // bt2 @ h + bt2_b + xs -> g_x
    gemmT<64,128,true,false><<<dim3(16,1,BB),128>>>(pwbt2, 64, phx, (size_t)128*NN,
        nullptr, bt2_b, phx + 64*NN, (size_t)128*NN, px, (size_t)64*NN, 64, NN, 0);
    // stacked qkv -> g_qkv [B][192][2048]
    gemmT<64,128,false,false><<<dim3(16,3,BB),128>>>(pwqkv, 192, px, (size_t)64*NN,
        nullptr, pbqkv, nullptr, 0, pqkv, (size_t)192*NN, 64, NN, 0);
    transpose192<<<dim3(64,6,BB), dim3(32,8)>>>(pqkv, pqkvt);

    // pos_enc
    posenc1<<<dim3(NK/32, BB), 256>>>(xyz, fd1_w);
    gemmT<64,128,false,false><<<dim3(256,1,BB),128>>>(pwfd2, 64, pt1, (size_t)64*NK,
        nullptr, fd2_b, nullptr, 0, ppos, (size_t)64*NK, 64, NK, 0);

    // attention MLP
    gv_build<<<512, 256>>>();
    gemmT<128,128,false,true><<<dim3(256,2,BB),256>>>(pwfg1, 256, pG, (size_t)64*NK,
        pfold+128, pfold+384, nullptr, 0, pH, (size_t)256*NK, 64, NK, 256);
    gemmT<64,128,false,false><<<dim3(256,1,BB),128>>>(pwfg2, 64, pH, (size_t)256*NK,
        nullptr, fg2_b, nullptr, 0, pat, (size_t)64*NK, 256, NK, 0);

    // fused upsample-attention + identity -> res
    k4_kernel<<<BB*NN, 256>>>(at_b, res);

    // completion head
    gemmT<64,128,false,false><<<dim3(64,1,BB),128>>>(pwm41, 64, res, (size_t)64*4*NN,
        nullptr, m41_b, nullptr, 0, pch, (size_t)64*4*NN, 64, 4*NN, 64);
    m42k<<<BB*4*NN/256, 256>>>(m42_w, m42_b, out);
}

// round 4
// speedup vs baseline: 1.4251x; 1.1214x over previous
#include <cuda_runtime.h>
#include <cstdint>

#define BB 4
#define NN 2048
#define KK 16
#define DD 64
#define NK (NN*KK)
#define EPSV 1e-5f

// ---------------- f32x2 packed FMA helpers ----------------
__device__ __forceinline__ uint64_t pk2(float lo, float hi){
    uint64_t r;
    asm("mov.b64 %0, {%1, %2};" : "=l"(r) : "r"(__float_as_uint(lo)), "r"(__float_as_uint(hi)));
    return r;
}
__device__ __forceinline__ void fma2(uint64_t& d, uint64_t a, uint64_t b){
    asm("fma.rn.f32x2 %0, %1, %2, %0;" : "+l"(d) : "l"(a), "l"(b));
}
__device__ __forceinline__ void unpk2(uint64_t v, float& lo, float& hi){
    uint32_t l, h;
    asm("mov.b64 {%0, %1}, %2;" : "=r"(l), "=r"(h) : "l"(v));
    lo = __uint_as_float(l); hi = __uint_as_float(h);
}

// ---------------- scratch (device globals) ----------------
__device__ float g_hx  [BB*128*NN];
__device__ float g_x   [BB*DD*NN];
__device__ float g_qkv [BB*192*NN];
__device__ float g_qkvt[BB*NN*192];
__device__ int   g_idx [BB*KK*NN];
__device__ float g_t1  [BB*DD*NK];
__device__ float g_pos [BB*DD*NK];
__device__ float g_G   [BB*DD*NK];
__device__ float g_vr  [BB*DD*NK];
__device__ float g_H   [(size_t)BB*256*NK];
__device__ float g_at  [BB*DD*NK];
__device__ float g_ch  [BB*DD*4*NN];
__device__ float g_fold[640];
__device__ float g_wT  [4*64*64];
__device__ float g_w_bt1s[480*128];
__device__ float g_b_bt1s[128];
__device__ float g_w_bt2 [64*64];
__device__ float g_w_qkv [64*192];
__device__ float g_b_qkv [192];
__device__ float g_w_fd2 [64*64];
__device__ float g_w_fg1 [64*256];
__device__ float g_w_fg2 [256*64];
__device__ float g_w_m41 [64*64];

// ---------------- prep ----------------
__global__ void prep_kernel(const float* __restrict__ fd_g, const float* __restrict__ fd1_b,
                            const float* __restrict__ fd_bb,
                            const float* __restrict__ fg_g, const float* __restrict__ fg1_b,
                            const float* __restrict__ fg_bb,
                            const float* __restrict__ at_w,
                            const float* __restrict__ bt1_w, const float* __restrict__ bt1_b,
                            const float* __restrict__ bts_w, const float* __restrict__ bts_b,
                            const float* __restrict__ bt2_w,
                            const float* __restrict__ q_w, const float* __restrict__ q_b,
                            const float* __restrict__ k_w, const float* __restrict__ k_b,
                            const float* __restrict__ v_w, const float* __restrict__ v_b,
                            const float* __restrict__ fd2_w,
                            const float* __restrict__ fg1_w, const float* __restrict__ fg2_w,
                            const float* __restrict__ m41_w)
{
    int t = blockIdx.x * blockDim.x + threadIdx.x;
    float inv = rsqrtf(1.f + EPSV);
    if (t < 64)  { float s = fd_g[t]*inv; g_fold[t] = s;     g_fold[64+t]  = fd1_b[t]*s + fd_bb[t]; }
    if (t < 256) { float s = fg_g[t]*inv; g_fold[128+t] = s; g_fold[384+t] = fg1_b[t]*s + fg_bb[t]; }
    if (t < 16384) {
        int r = t & 3, o = (t >> 2) & 63, c = t >> 8;
        g_wT[r*4096 + c*64 + o] = at_w[t];
        { int k = t >> 8, m = t & 255; g_w_fg1[k*256 + m] = fg1_w[m*64 + k]; }
        { int k = t >> 6, m = t & 63;  g_w_fg2[k*64 + m]  = fg2_w[m*256 + k]; }
    }
    if (t < 61440) { int k = t >> 7, m = t & 127;
        g_w_bt1s[t] = (m < 64) ? bt1_w[m*480 + k] : bts_w[(m-64)*480 + k]; }
    if (t < 128) g_b_bt1s[t] = (t < 64) ? bt1_b[t] : bts_b[t-64];
    if (t < 12288) { int k = t / 192, m = t % 192;
        g_w_qkv[t] = (m < 64) ? q_w[m*64+k] : (m < 128 ? k_w[(m-64)*64+k] : v_w[(m-128)*64+k]); }
    if (t < 192) g_b_qkv[t] = (t < 64) ? q_b[t] : (t < 128 ? k_b[t-64] : v_b[t-128]);
    if (t < 4096) { int k = t >> 6, m = t & 63;
        g_w_bt2[t] = bt2_w[m*64+k];
        g_w_fd2[t] = fd2_w[m*64+k];
        g_w_m41[t] = m41_w[m*64+k]; }
}

// ---------------- KNN ----------------
__global__ void knn_kernel(const float* __restrict__ xyz)
{
    __shared__ float sx[NN], sy[NN], sz[NN], ssq[NN];
    int b  = blockIdx.x >> 7;
    int n0 = (blockIdx.x & 127) * 16;
    const float* xb = xyz + b*3*NN;
    for (int m = threadIdx.x; m < NN; m += blockDim.x) {
        float px = xb[m], py = xb[NN+m], pz = xb[2*NN+m];
        sx[m]=px; sy[m]=py; sz[m]=pz; ssq[m] = px*px + py*py + pz*pz;
    }
    __syncthreads();
    int warp = threadIdx.x >> 5, lane = threadIdx.x & 31;
    int n = n0 + warp;
    float px = sx[n], py = sy[n], pz = sz[n], sqn = ssq[n];

    float bv[17]; int bi[17];
    #pragma unroll
    for (int i = 0; i < 17; i++) { bv[i] = 3.4e38f; bi[i] = 0x7fffffff; }
    for (int m = lane; m < NN; m += 32) {
        float d2 = sqn + ssq[m] - 2.f*(px*sx[m] + py*sy[m] + pz*sz[m]);
        if (d2 < bv[16]) {
            bv[16] = d2; bi[16] = m;
            #pragma unroll
            for (int s = 16; s > 0; --s)
                if (bv[s] < bv[s-1]) {
                    float tv = bv[s]; bv[s] = bv[s-1]; bv[s-1] = tv;
                    int   ti = bi[s]; bi[s] = bi[s-1]; bi[s-1] = ti;
                }
        }
    }
    for (int t = 0; t < 17; ++t) {
        float hv = bv[0]; int hi = bi[0];
        float v = hv; int id = hi;
        #pragma unroll
        for (int off = 16; off; off >>= 1) {
            float ov = __shfl_xor_sync(0xffffffffu, v, off);
            int   oi = __shfl_xor_sync(0xffffffffu, id, off);
            if (ov < v || (ov == v && oi < id)) { v = ov; id = oi; }
        }
        if (t > 0 && lane == 0) g_idx[b*KK*NN + (t-1)*NN + n] = id;
        if (hv == v && hi == id) {
            #pragma unroll
            for (int s = 0; s < 16; ++s) { bv[s] = bv[s+1]; bi[s] = bi[s+1]; }
            bv[16] = 3.4e38f; bi[16] = 0x7fffffff;
        }
    }
}

// ---------------- tiled fp32 GEMM with packed FFMA2 inner loop ----------------
template<int BM, int BN, bool ADD, bool SCALE>
__global__ void __launch_bounds__((BM/8)*(BN/8))
gemmT(const float* __restrict__ Wt, int ldw,
      const float* __restrict__ X, size_t xbs,
      const float* __restrict__ scale, const float* __restrict__ bias,
      const float* __restrict__ S, size_t sbs,
      float* __restrict__ C, size_t cbs,
      int Kd, int Nc, int relu_rows)
{
    constexpr int KC = 8;
    constexpr int NTH = (BM/8)*(BN/8);
    constexpr int W4 = KC*BM/4, X4 = KC*BN/4;
    constexpr int WPT = (W4 + NTH - 1)/NTH, XPT = (X4 + NTH - 1)/NTH;
    __shared__ __align__(16) float sW[2][KC][BM];
    __shared__ __align__(16) float sX[2][KC][BN];
    int tid = threadIdx.x;
    int bn0 = blockIdx.x * BN;
    int bm0 = blockIdx.y * BM;
    const float* Xb = X + (size_t)blockIdx.z * xbs;
    const float* Sb = S ? S + (size_t)blockIdx.z * sbs : nullptr;
    float* Cb = C + (size_t)blockIdx.z * cbs;

    float4 wr[WPT], xr[XPT];
    uint64_t acc2[8][4];
    #pragma unroll
    for (int i = 0; i < 8; i++)
        #pragma unroll
        for (int j = 0; j < 4; j++) acc2[i][j] = 0ull;
    int tx = tid % (BN/8), ty = tid / (BN/8);
    int rm = ty*8, rn = tx*8;
    int nch = Kd / KC;

    {
        #pragma unroll
        for (int i = 0; i < WPT; i++) { int t = tid + i*NTH; if (t < W4) {
            int k = t/(BM/4), m4 = t%(BM/4);
            wr[i] = *(const float4*)(Wt + (size_t)k*ldw + bm0 + m4*4); } }
        #pragma unroll
        for (int i = 0; i < XPT; i++) { int t = tid + i*NTH; if (t < X4) {
            int k = t/(BN/4), n4 = t%(BN/4);
            xr[i] = *(const float4*)(Xb + (size_t)k*Nc + bn0 + n4*4); } }
        #pragma unroll
        for (int i = 0; i < WPT; i++) { int t = tid + i*NTH; if (t < W4) {
            int k = t/(BM/4), m4 = t%(BM/4); *(float4*)&sW[0][k][m4*4] = wr[i]; } }
        #pragma unroll
        for (int i = 0; i < XPT; i++) { int t = tid + i*NTH; if (t < X4) {
            int k = t/(BN/4), n4 = t%(BN/4); *(float4*)&sX[0][k][n4*4] = xr[i]; } }
    }
    __syncthreads();

    for (int c = 0; c < nch; ++c) {
        if (c + 1 < nch) {
            int k0 = (c+1)*KC;
            #pragma unroll
            for (int i = 0; i < WPT; i++) { int t = tid + i*NTH; if (t < W4) {
                int k = t/(BM/4), m4 = t%(BM/4);
                wr[i] = *(const float4*)(Wt + (size_t)(k0+k)*ldw + bm0 + m4*4); } }
            #pragma unroll
            for (int i = 0; i < XPT; i++) { int t = tid + i*NTH; if (t < X4) {
                int k = t/(BN/4), n4 = t%(BN/4);
                xr[i] = *(const float4*)(Xb + (size_t)(k0+k)*Nc + bn0 + n4*4); } }
        }
        int buf = c & 1;
        #pragma unroll
        for (int k = 0; k < KC; ++k) {
            // b operands read directly as packed f32x2 pairs from smem
            ulonglong2 bq0 = *(const ulonglong2*)&sX[buf][k][rn];
            ulonglong2 bq1 = *(const ulonglong2*)&sX[buf][k][rn+4];
            uint64_t bp[4] = {bq0.x, bq0.y, bq1.x, bq1.y};
            float4 a0 = *(const float4*)&sW[buf][k][rm];
            float4 a1 = *(const float4*)&sW[buf][k][rm+4];
            float av[8] = {a0.x,a0.y,a0.z,a0.w,a1.x,a1.y,a1.z,a1.w};
            uint64_t ap[8];
            #pragma unroll
            for (int i = 0; i < 8; i++) ap[i] = pk2(av[i], av[i]);
            #pragma unroll
            for (int i = 0; i < 8; i++)
                #pragma unroll
                for (int j = 0; j < 4; j++) fma2(acc2[i][j], ap[i], bp[j]);
        }
        if (c + 1 < nch) {
            int nb = (c+1) & 1;
            #pragma unroll
            for (int i = 0; i < WPT; i++) { int t = tid + i*NTH; if (t < W4) {
                int k = t/(BM/4), m4 = t%(BM/4); *(float4*)&sW[nb][k][m4*4] = wr[i]; } }
            #pragma unroll
            for (int i = 0; i < XPT; i++) { int t = tid + i*NTH; if (t < X4) {
                int k = t/(BN/4), n4 = t%(BN/4); *(float4*)&sX[nb][k][n4*4] = xr[i]; } }
        }
        __syncthreads();
    }

    #pragma unroll
    for (int i = 0; i < 8; i++) {
        int row = bm0 + rm + i;
        float sc = SCALE ? scale[row] : 1.f;
        float bs = bias[row];
        bool rl = row < relu_rows;
        float v[8];
        #pragma unroll
        for (int j = 0; j < 4; j++) unpk2(acc2[i][j], v[2*j], v[2*j+1]);
        #pragma unroll
        for (int j = 0; j < 8; j++) {
            float t = v[j]*sc + bs;
            if (ADD) t += Sb[(size_t)row*Nc + bn0 + rn + j];
            v[j] = rl ? fmaxf(t, 0.f) : t;
        }
        *(float4*)(Cb + (size_t)row*Nc + bn0 + rn)     = make_float4(v[0],v[1],v[2],v[3]);
        *(float4*)(Cb + (size_t)row*Nc + bn0 + rn + 4) = make_float4(v[4],v[5],v[6],v[7]);
    }
}

// ---------------- transpose ----------------
__global__ void transpose192(const float* __restrict__ src, float* __restrict__ dst)
{
    __shared__ float tile[32][33];
    int b = blockIdx.z;
    int n0 = blockIdx.x*32, c0 = blockIdx.y*32;
    const float* s = src + (size_t)b*192*NN;
    float* d = dst + (size_t)b*NN*192;
    for (int i = threadIdx.y; i < 32; i += 8)
        tile[i][threadIdx.x] = s[(size_t)(c0+i)*NN + n0 + threadIdx.x];
    __syncthreads();
    for (int i = threadIdx.y; i < 32; i += 8)
        d[(size_t)(n0+i)*192 + c0 + threadIdx.x] = tile[threadIdx.x][i];
}

// ---------------- fused rel_xyz + fd1 ----------------
__global__ void posenc1(const float* __restrict__ xyz, const float* __restrict__ fd1_w)
{
    __shared__ float srel[3][32];
    int b = blockIdx.y;
    int base = blockIdx.x * 32;
    int tid = threadIdx.x;
    if (tid < 32) {
        int col = base + tid;
        int n = col >> 4, j = col & 15;
        int id = g_idx[b*KK*NN + j*NN + n];
        const float* xb = xyz + b*3*NN;
        srel[0][tid] = xb[n]      - xb[id];
        srel[1][tid] = xb[NN+n]   - xb[NN+id];
        srel[2][tid] = xb[2*NN+n] - xb[2*NN+id];
    }
    __syncthreads();
    int lane = tid & 31, w = tid >> 5;
    float rx = srel[0][lane], ry = srel[1][lane], rz = srel[2][lane];
    #pragma unroll
    for (int it = 0; it < 8; ++it) {
        int m = it*8 + w;
        float v = fd1_w[m*3]*rx + fd1_w[m*3+1]*ry + fd1_w[m*3+2]*rz;
        v = fmaxf(v * g_fold[m] + g_fold[64+m], 0.f);
        g_t1[(size_t)(b*64+m)*NK + base + lane] = v;
    }
}

// ---------------- G / Vrel build with vectorized gathers ----------------
__global__ void gv_build()
{
    int t = blockIdx.x*blockDim.x + threadIdx.x;
    if (t >= BB*NN*KK) return;
    int j = t & 15; int n = (t >> 4) & 2047; int b = t >> 15;
    int id = g_idx[b*KK*NN + j*NN + n];
    const float4* qt = (const float4*)(g_qkvt + ((size_t)b*NN + n )*192);
    const float4* kt = (const float4*)(g_qkvt + ((size_t)b*NN + id)*192 + 64);
    const float4* vt = (const float4*)(g_qkvt + ((size_t)b*NN + id)*192 + 128);
    #pragma unroll 4
    for (int c4 = 0; c4 < 16; c4++) {
        float4 qv = qt[c4], kv = kt[c4], vv = vt[c4];
        size_t off = ((size_t)(b*DD + c4*4)*NN + n)*KK + j;
        float p0 = g_pos[off], p1 = g_pos[off+NK], p2 = g_pos[off+2*NK], p3 = g_pos[off+3*NK];
        g_G[off]        = qv.x - kv.x + p0;
        g_G[off+NK]     = qv.y - kv.y + p1;
        g_G[off+2*NK]   = qv.z - kv.z + p2;
        g_G[off+3*NK]   = qv.w - kv.w + p3;
        g_vr[off]       = vv.x + p0;
        g_vr[off+NK]    = vv.y + p1;
        g_vr[off+2*NK]  = vv.z + p2;
        g_vr[off+3*NK]  = vv.w + p3;
    }
}

// ---------------- fused ConvT(4,1) + softmax + weighted sum + identity (FFMA2) ----------------
__global__ void __launch_bounds__(256) k4_kernel(const float* __restrict__ at_b,
                                                 float* __restrict__ res_out)
{
    __shared__ __align__(16) float s_a[64*16];
    __shared__ float s_v[16*64];
    __shared__ float s_m[16][8];
    __shared__ float s_s[16][8];
    __shared__ float s_out[256];
    int bn = blockIdx.x;
    int b = bn >> 11, n = bn & 2047;
    int tid = threadIdx.x;
    int o = tid & 63, r = tid >> 6;
    int lane = tid & 31, warp = tid >> 5;
    {
        int c = tid >> 2, fq = (tid & 3) * 4;
        size_t base = ((size_t)(b*64 + c)*2048 + n)*16 + fq;
        float4 a4 = *(const float4*)(g_at + base);
        *(float4*)(s_a + c*16 + fq) = a4;
        float4 v4 = *(const float4*)(g_vr + base);
        s_v[(fq+0)*64 + c] = v4.x;
        s_v[(fq+1)*64 + c] = v4.y;
        s_v[(fq+2)*64 + c] = v4.z;
        s_v[(fq+3)*64 + c] = v4.w;
    }
    __syncthreads();

    float bo = at_b[o];
    uint64_t y2[8];
    uint64_t bo2 = pk2(bo, bo);
    #pragma unroll
    for (int f = 0; f < 8; f++) y2[f] = bo2;
    const float* w = g_wT + r*4096 + o;
    #pragma unroll 4
    for (int c = 0; c < 64; c++) {
        uint64_t wp = pk2(w[c*64], w[c*64]);
        const ulonglong2* ap = (const ulonglong2*)(s_a + c*16);
        ulonglong2 q0 = ap[0], q1 = ap[1];
        fma2(y2[0], wp, q0.x); fma2(y2[1], wp, q0.y);
        fma2(y2[2], wp, q1.x); fma2(y2[3], wp, q1.y);
        ulonglong2 q2 = ap[2], q3 = ap[3];
        fma2(y2[4], wp, q2.x); fma2(y2[5], wp, q2.y);
        fma2(y2[6], wp, q3.x); fma2(y2[7], wp, q3.y);
    }
    float y[16];
    #pragma unroll
    for (int f = 0; f < 8; f++) unpk2(y2[f], y[2*f], y[2*f+1]);

    #pragma unroll
    for (int f = 0; f < 16; f++) {
        float m = y[f];
        #pragma unroll
        for (int off = 16; off; off >>= 1) m = fmaxf(m, __shfl_xor_sync(0xffffffffu, m, off));
        if (lane == 0) s_m[f][warp] = m;
    }
    __syncthreads();
    #pragma unroll
    for (int f = 0; f < 16; f++) {
        float m = fmaxf(s_m[f][2*r], s_m[f][2*r+1]);
        float e = __expf(y[f] - m);
        y[f] = e;
        float sm = e;
        #pragma unroll
        for (int off = 16; off; off >>= 1) sm += __shfl_xor_sync(0xffffffffu, sm, off);
        if (lane == 0) s_s[f][warp] = sm;
    }
    __syncthreads();
    float acc = 0.f;
    #pragma unroll
    for (int f = 0; f < 16; f++) {
        float sum = s_s[f][2*r] + s_s[f][2*r+1];
        acc = fmaf(y[f] / sum, s_v[f*64 + o], acc);
    }
    acc += g_x[(size_t)b*131072 + o*2048 + n];
    s_out[o*4 + r] = acc;
    __syncthreads();
    if (tid < 64) {
        float4 ov = *(const float4*)(s_out + tid*4);
        *(float4*)(res_out + (size_t)b*524288 + (size_t)tid*8192 + n*4) = ov;
    }
}

// ---------------- m42 ----------------
__global__ void m42k(const float* __restrict__ w, const float* __restrict__ bias,
                     float* __restrict__ out)
{
    int t = blockIdx.x*blockDim.x + threadIdx.x;
    int col = t & 8191, b = t >> 13;
    float a0 = bias[0], a1 = bias[1], a2 = bias[2];
    const float* ch = g_ch + (size_t)b*524288 + col;
    #pragma unroll 8
    for (int c = 0; c < 64; c++) {
        float xv = ch[(size_t)c*8192];
        a0 = fmaf(w[c], xv, a0);
        a1 = fmaf(w[64+c], xv, a1);
        a2 = fmaf(w[128+c], xv, a2);
    }
    out[(size_t)(b*3+0)*8192 + col] = a0;
    out[(size_t)(b*3+1)*8192 + col] = a1;
    out[(size_t)(b*3+2)*8192 + col] = a2;
}

// ---------------- launch ----------------
extern "C" void kernel_launch(void* const* d_in, const int* in_sizes, int n_in,
                              void* d_out, int out_size)
{
    const float* feature = (const float*)d_in[0];
    const float* xyz     = (const float*)d_in[1];
    const float* bt1_w = (const float*)d_in[2];  const float* bt1_b = (const float*)d_in[3];
    const float* bt2_w = (const float*)d_in[4];  const float* bt2_b = (const float*)d_in[5];
    const float* bts_w = (const float*)d_in[6];  const float* bts_b = (const float*)d_in[7];
    const float* q_w   = (const float*)d_in[8];  const float* q_b   = (const float*)d_in[9];
    const float* k_w   = (const float*)d_in[10]; const float* k_b   = (const float*)d_in[11];
    const float* v_w   = (const float*)d_in[12]; const float* v_b   = (const float*)d_in[13];
    const float* fd1_w = (const float*)d_in[14]; const float* fd1_b = (const float*)d_in[15];
    const float* fd_g  = (const float*)d_in[16]; const float* fd_bb = (const float*)d_in[17];
    const float* fd2_w = (const float*)d_in[18]; const float* fd2_b = (const float*)d_in[19];
    const float* fg1_w = (const float*)d_in[20]; const float* fg1_b = (const float*)d_in[21];
    const float* fg_g  = (const float*)d_in[22]; const float* fg_bb = (const float*)d_in[23];
    const float* fg2_w = (const float*)d_in[24]; const float* fg2_b = (const float*)d_in[25];
    const float* at_w  = (const float*)d_in[26]; const float* at_b  = (const float*)d_in[27];
    const float* m41_w = (const float*)d_in[28]; const float* m41_b = (const float*)d_in[29];
    const float* m42_w = (const float*)d_in[30]; const float* m42_b = (const float*)d_in[31];

    float *phx, *px, *pqkv, *pqkvt, *pt1, *ppos, *pG, *pH, *pat, *pch, *pfold;
    float *pwbt1s, *pbbt1s, *pwbt2, *pwqkv, *pbqkv, *pwfd2, *pwfg1, *pwfg2, *pwm41;
    cudaGetSymbolAddress((void**)&phx,   g_hx);
    cudaGetSymbolAddress((void**)&px,    g_x);
    cudaGetSymbolAddress((void**)&pqkv,  g_qkv);
    cudaGetSymbolAddress((void**)&pqkvt, g_qkvt);
    cudaGetSymbolAddress((void**)&pt1,   g_t1);
    cudaGetSymbolAddress((void**)&ppos,  g_pos);
    cudaGetSymbolAddress((void**)&pG,    g_G);
    cudaGetSymbolAddress((void**)&pH,    g_H);
    cudaGetSymbolAddress((void**)&pat,   g_at);
    cudaGetSymbolAddress((void**)&pch,   g_ch);
    cudaGetSymbolAddress((void**)&pfold, g_fold);
    cudaGetSymbolAddress((void**)&pwbt1s,g_w_bt1s);
    cudaGetSymbolAddress((void**)&pbbt1s,g_b_bt1s);
    cudaGetSymbolAddress((void**)&pwbt2, g_w_bt2);
    cudaGetSymbolAddress((void**)&pwqkv, g_w_qkv);
    cudaGetSymbolAddress((void**)&pbqkv, g_b_qkv);
    cudaGetSymbolAddress((void**)&pwfd2, g_w_fd2);
    cudaGetSymbolAddress((void**)&pwfg1, g_w_fg1);
    cudaGetSymbolAddress((void**)&pwfg2, g_w_fg2);
    cudaGetSymbolAddress((void**)&pwm41, g_w_m41);

    float* out = (float*)d_out;
    float* res = out + BB*3*4*NN;

    prep_kernel<<<256, 256>>>(fd_g, fd1_b, fd_bb, fg_g, fg1_b, fg_bb, at_w,
                              bt1_w, bt1_b, bts_w, bts_b, bt2_w,
                              q_w, q_b, k_w, k_b, v_w, v_b,
                              fd2_w, fg1_w, fg2_w, m41_w);
    knn_kernel<<<BB*NN/16, 512>>>(xyz);

    gemmT<128,64,false,false><<<dim3(32,1,BB),128>>>(pwbt1s, 128, feature, (size_t)480*NN,
        nullptr, pbbt1s, nullptr, 0, phx, (size_t)128*NN, 480, NN, 64);
    gemmT<64,128,true,false><<<dim3(16,1,BB),128>>>(pwbt2, 64, phx, (size_t)128*NN,
        nullptr, bt2_b, phx + 64*NN, (size_t)128*NN, px, (size_t)64*NN, 64, NN, 0);
    gemmT<64,128,false,false><<<dim3(16,3,BB),128>>>(pwqkv, 192, px, (size_t)64*NN,
        nullptr, pbqkv, nullptr, 0, pqkv, (size_t)192*NN, 64, NN, 0);
    transpose192<<<dim3(64,6,BB), dim3(32,8)>>>(pqkv, pqkvt);

    posenc1<<<dim3(NK/32, BB), 256>>>(xyz, fd1_w);
    gemmT<64,128,false,false><<<dim3(256,1,BB),128>>>(pwfd2, 64, pt1, (size_t)64*NK,
        nullptr, fd2_b, nullptr, 0, ppos, (size_t)64*NK, 64, NK, 0);

    gv_build<<<512, 256>>>();
    gemmT<128,128,false,true><<<dim3(256,2,BB),256>>>(pwfg1, 256, pG, (size_t)64*NK,
        pfold+128, pfold+384, nullptr, 0, pH, (size_t)256*NK, 64, NK, 256);
    gemmT<64,128,false,false><<<dim3(256,1,BB),128>>>(pwfg2, 64, pH, (size_t)256*NK,
        nullptr, fg2_b, nullptr, 0, pat, (size_t)64*NK, 256, NK, 0);

    k4_kernel<<<BB*NN, 256>>>(at_b, res);

    gemmT<64,128,false,false><<<dim3(64,1,BB),128>>>(pwm41, 64, res, (size_t)64*4*NN,
        nullptr, m41_b, nullptr, 0, pch, (size_t)64*4*NN, 64, 4*NN, 64);
    m42k<<<BB*4*NN/256, 256>>>(m42_w, m42_b, out);
}

// round 5
// speedup vs baseline: 1.5053x; 1.0563x over previous
#include <cuda_runtime.h>
#include <cstdint>

#define BB 4
#define NN 2048
#define KK 16
#define DD 64
#define NK (NN*KK)
#define EPSV 1e-5f

// ---------------- f32x2 packed FMA helpers ----------------
__device__ __forceinline__ uint64_t pk2(float lo, float hi){
    uint64_t r;
    asm("mov.b64 %0, {%1, %2};" : "=l"(r) : "r"(__float_as_uint(lo)), "r"(__float_as_uint(hi)));
    return r;
}
__device__ __forceinline__ void fma2(uint64_t& d, uint64_t a, uint64_t b){
    asm("fma.rn.f32x2 %0, %1, %2, %0;" : "+l"(d) : "l"(a), "l"(b));
}
__device__ __forceinline__ void unpk2(uint64_t v, float& lo, float& hi){
    uint32_t l, h;
    asm("mov.b64 {%0, %1}, %2;" : "=r"(l), "=r"(h) : "l"(v));
    lo = __uint_as_float(l); hi = __uint_as_float(h);
}

// ---------------- scratch ----------------
__device__ float g_hx  [BB*128*NN];
__device__ float g_x   [BB*DD*NN];
__device__ float g_qkvt[BB*NN*192];
__device__ int   g_idx [BB*KK*NN];
__device__ float g_t1  [BB*DD*NK];
__device__ float g_G   [BB*DD*NK];
__device__ float g_vr  [BB*DD*NK];
__device__ float g_at  [BB*DD*NK];
__device__ float g_fold[640];
__device__ float g_wT  [4*64*64];
__device__ float g_w_bt1s[480*128];
__device__ float g_b_bt1s[128];
__device__ float g_w_bt2 [64*64];
__device__ float g_w_qkv [64*192];
__device__ float g_b_qkv [192];
__device__ float g_w_fd2 [64*64];
__device__ float g_w_fg1 [64*256];
__device__ float g_w_fg2 [256*64];
__device__ float g_w_m41 [64*64];

// ---------------- prep ----------------
__global__ void prep_kernel(const float* __restrict__ fd_g, const float* __restrict__ fd1_b,
                            const float* __restrict__ fd_bb,
                            const float* __restrict__ fg_g, const float* __restrict__ fg1_b,
                            const float* __restrict__ fg_bb,
                            const float* __restrict__ at_w,
                            const float* __restrict__ bt1_w, const float* __restrict__ bt1_b,
                            const float* __restrict__ bts_w, const float* __restrict__ bts_b,
                            const float* __restrict__ bt2_w,
                            const float* __restrict__ q_w, const float* __restrict__ q_b,
                            const float* __restrict__ k_w, const float* __restrict__ k_b,
                            const float* __restrict__ v_w, const float* __restrict__ v_b,
                            const float* __restrict__ fd2_w,
                            const float* __restrict__ fg1_w, const float* __restrict__ fg2_w,
                            const float* __restrict__ m41_w)
{
    int t = blockIdx.x * blockDim.x + threadIdx.x;
    float inv = rsqrtf(1.f + EPSV);
    if (t < 64)  { float s = fd_g[t]*inv; g_fold[t] = s;     g_fold[64+t]  = fd1_b[t]*s + fd_bb[t]; }
    if (t < 256) { float s = fg_g[t]*inv; g_fold[128+t] = s; g_fold[384+t] = fg1_b[t]*s + fg_bb[t]; }
    if (t < 16384) {
        int r = t & 3, o = (t >> 2) & 63, c = t >> 8;
        g_wT[r*4096 + c*64 + o] = at_w[t];
        { int k = t >> 8, m = t & 255; g_w_fg1[k*256 + m] = fg1_w[m*64 + k]; }
        { int k = t >> 6, m = t & 63;  g_w_fg2[k*64 + m]  = fg2_w[m*256 + k]; }
    }
    if (t < 61440) { int k = t >> 7, m = t & 127;
        g_w_bt1s[t] = (m < 64) ? bt1_w[m*480 + k] : bts_w[(m-64)*480 + k]; }
    if (t < 128) g_b_bt1s[t] = (t < 64) ? bt1_b[t] : bts_b[t-64];
    if (t < 12288) { int k = t / 192, m = t % 192;
        g_w_qkv[t] = (m < 64) ? q_w[m*64+k] : (m < 128 ? k_w[(m-64)*64+k] : v_w[(m-128)*64+k]); }
    if (t < 192) g_b_qkv[t] = (t < 64) ? q_b[t] : (t < 128 ? k_b[t-64] : v_b[t-128]);
    if (t < 4096) { int k = t >> 6, m = t & 63;
        g_w_bt2[t] = bt2_w[m*64+k];
        g_w_fd2[t] = fd2_w[m*64+k];
        g_w_m41[t] = m41_w[m*64+k]; }
}

// ---------------- KNN ----------------
__global__ void knn_kernel(const float* __restrict__ xyz)
{
    __shared__ float sx[NN], sy[NN], sz[NN], ssq[NN];
    int b  = blockIdx.x >> 7;
    int n0 = (blockIdx.x & 127) * 16;
    const float* xb = xyz + b*3*NN;
    for (int m = threadIdx.x; m < NN; m += blockDim.x) {
        float px = xb[m], py = xb[NN+m], pz = xb[2*NN+m];
        sx[m]=px; sy[m]=py; sz[m]=pz; ssq[m] = px*px + py*py + pz*pz;
    }
    __syncthreads();
    int warp = threadIdx.x >> 5, lane = threadIdx.x & 31;
    int n = n0 + warp;
    float px = sx[n], py = sy[n], pz = sz[n], sqn = ssq[n];

    float bv[17]; int bi[17];
    #pragma unroll
    for (int i = 0; i < 17; i++) { bv[i] = 3.4e38f; bi[i] = 0x7fffffff; }
    for (int m = lane; m < NN; m += 32) {
        float d2 = sqn + ssq[m] - 2.f*(px*sx[m] + py*sy[m] + pz*sz[m]);
        if (d2 < bv[16]) {
            bv[16] = d2; bi[16] = m;
            #pragma unroll
            for (int s = 16; s > 0; --s)
                if (bv[s] < bv[s-1]) {
                    float tv = bv[s]; bv[s] = bv[s-1]; bv[s-1] = tv;
                    int   ti = bi[s]; bi[s] = bi[s-1]; bi[s-1] = ti;
                }
        }
    }
    for (int t = 0; t < 17; ++t) {
        float hv = bv[0]; int hi = bi[0];
        float v = hv; int id = hi;
        #pragma unroll
        for (int off = 16; off; off >>= 1) {
            float ov = __shfl_xor_sync(0xffffffffu, v, off);
            int   oi = __shfl_xor_sync(0xffffffffu, id, off);
            if (ov < v || (ov == v && oi < id)) { v = ov; id = oi; }
        }
        if (t > 0 && lane == 0) g_idx[b*KK*NN + (t-1)*NN + n] = id;
        if (hv == v && hi == id) {
            #pragma unroll
            for (int s = 0; s < 16; ++s) { bv[s] = bv[s+1]; bi[s] = bi[s+1]; }
            bv[16] = 3.4e38f; bi[16] = 0x7fffffff;
        }
    }
}

// ---------------- gemmT (used for bt1s only, K=480) ----------------
template<int BM, int BN>
__global__ void __launch_bounds__((BM/8)*(BN/8))
gemmT(const float* __restrict__ Wt, int ldw,
      const float* __restrict__ X, size_t xbs,
      const float* __restrict__ bias,
      float* __restrict__ C, size_t cbs,
      int Kd, int Nc, int relu_rows)
{
    constexpr int KC = 8;
    constexpr int NTH = (BM/8)*(BN/8);
    constexpr int W4 = KC*BM/4, X4 = KC*BN/4;
    constexpr int WPT = (W4 + NTH - 1)/NTH, XPT = (X4 + NTH - 1)/NTH;
    __shared__ __align__(16) float sW[2][KC][BM];
    __shared__ __align__(16) float sX[2][KC][BN];
    int tid = threadIdx.x;
    int bn0 = blockIdx.x * BN;
    int bm0 = blockIdx.y * BM;
    const float* Xb = X + (size_t)blockIdx.z * xbs;
    float* Cb = C + (size_t)blockIdx.z * cbs;

    float4 wr[WPT], xr[XPT];
    uint64_t acc2[8][4];
    #pragma unroll
    for (int i = 0; i < 8; i++)
        #pragma unroll
        for (int j = 0; j < 4; j++) acc2[i][j] = 0ull;
    int tx = tid % (BN/8), ty = tid / (BN/8);
    int rm = ty*8, rn = tx*8;
    int nch = Kd / KC;

    {
        #pragma unroll
        for (int i = 0; i < WPT; i++) { int t = tid + i*NTH; if (t < W4) {
            int k = t/(BM/4), m4 = t%(BM/4);
            wr[i] = *(const float4*)(Wt + (size_t)k*ldw + bm0 + m4*4); } }
        #pragma unroll
        for (int i = 0; i < XPT; i++) { int t = tid + i*NTH; if (t < X4) {
            int k = t/(BN/4), n4 = t%(BN/4);
            xr[i] = *(const float4*)(Xb + (size_t)k*Nc + bn0 + n4*4); } }
        #pragma unroll
        for (int i = 0; i < WPT; i++) { int t = tid + i*NTH; if (t < W4) {
            int k = t/(BM/4), m4 = t%(BM/4); *(float4*)&sW[0][k][m4*4] = wr[i]; } }
        #pragma unroll
        for (int i = 0; i < XPT; i++) { int t = tid + i*NTH; if (t < X4) {
            int k = t/(BN/4), n4 = t%(BN/4); *(float4*)&sX[0][k][n4*4] = xr[i]; } }
    }
    __syncthreads();

    for (int c = 0; c < nch; ++c) {
        if (c + 1 < nch) {
            int k0 = (c+1)*KC;
            #pragma unroll
            for (int i = 0; i < WPT; i++) { int t = tid + i*NTH; if (t < W4) {
                int k = t/(BM/4), m4 = t%(BM/4);
                wr[i] = *(const float4*)(Wt + (size_t)(k0+k)*ldw + bm0 + m4*4); } }
            #pragma unroll
            for (int i = 0; i < XPT; i++) { int t = tid + i*NTH; if (t < X4) {
                int k = t/(BN/4), n4 = t%(BN/4);
                xr[i] = *(const float4*)(Xb + (size_t)(k0+k)*Nc + bn0 + n4*4); } }
        }
        int buf = c & 1;
        #pragma unroll
        for (int k = 0; k < KC; ++k) {
            ulonglong2 bq0 = *(const ulonglong2*)&sX[buf][k][rn];
            ulonglong2 bq1 = *(const ulonglong2*)&sX[buf][k][rn+4];
            uint64_t bp[4] = {bq0.x, bq0.y, bq1.x, bq1.y};
            float4 a0 = *(const float4*)&sW[buf][k][rm];
            float4 a1 = *(const float4*)&sW[buf][k][rm+4];
            float av[8] = {a0.x,a0.y,a0.z,a0.w,a1.x,a1.y,a1.z,a1.w};
            #pragma unroll
            for (int i = 0; i < 8; i++) {
                uint64_t ap = pk2(av[i], av[i]);
                #pragma unroll
                for (int j = 0; j < 4; j++) fma2(acc2[i][j], ap, bp[j]);
            }
        }
        if (c + 1 < nch) {
            int nb = (c+1) & 1;
            #pragma unroll
            for (int i = 0; i < WPT; i++) { int t = tid + i*NTH; if (t < W4) {
                int k = t/(BM/4), m4 = t%(BM/4); *(float4*)&sW[nb][k][m4*4] = wr[i]; } }
            #pragma unroll
            for (int i = 0; i < XPT; i++) { int t = tid + i*NTH; if (t < X4) {
                int k = t/(BN/4), n4 = t%(BN/4); *(float4*)&sX[nb][k][n4*4] = xr[i]; } }
        }
        __syncthreads();
    }

    #pragma unroll
    for (int i = 0; i < 8; i++) {
        int row = bm0 + rm + i;
        float bs = bias[row];
        bool rl = row < relu_rows;
        float v[8];
        #pragma unroll
        for (int j = 0; j < 4; j++) unpk2(acc2[i][j], v[2*j], v[2*j+1]);
        #pragma unroll
        for (int j = 0; j < 8; j++) {
            float t = v[j] + bs;
            v[j] = rl ? fmaxf(t, 0.f) : t;
        }
        *(float4*)(Cb + (size_t)row*Nc + bn0 + rn)     = make_float4(v[0],v[1],v[2],v[3]);
        *(float4*)(Cb + (size_t)row*Nc + bn0 + rn + 4) = make_float4(v[4],v[5],v[6],v[7]);
    }
}

// ---------------- fused bt2 + qkv + transpose ----------------
// grid (16,1,BB), 128 threads. smem: sWb[64][68] + sh[64][132] + sx[64][132]
__global__ void __launch_bounds__(128) bt2qkv_kernel(const float* __restrict__ bt2_b)
{
    extern __shared__ __align__(16) float dynC[];
    float* sWb = dynC;                 // [64][68]
    float* sh  = dynC + 64*68;         // [64][132]
    float* sx  = dynC + 64*68 + 64*132;// [64][132]
    int tid = threadIdx.x;
    int b = blockIdx.z;
    int bn0 = blockIdx.x * 128;
    int tx = tid & 15, ty = tid >> 4;
    int rn = tx*8, rm = ty*8;

    #pragma unroll
    for (int i = 0; i < 8; i++) { int t = tid + i*128; int k = t>>4, m4 = (t&15)*4;
        *(float4*)&sWb[k*68 + m4] = *(const float4*)(g_w_bt2 + k*64 + m4); }
    #pragma unroll
    for (int i = 0; i < 16; i++) { int t = tid + i*128; int k = t>>5, f = (t&31)*4;
        *(float4*)&sh[k*132 + f] = *(const float4*)(g_hx + ((size_t)(b*128+k))*NN + bn0 + f); }
    __syncthreads();

    uint64_t acc[8][4];
    #pragma unroll
    for (int i = 0; i < 8; i++)
        #pragma unroll
        for (int j = 0; j < 4; j++) acc[i][j] = 0ull;
    #pragma unroll 4
    for (int k = 0; k < 64; ++k) {
        ulonglong2 b0 = *(const ulonglong2*)&sh[k*132 + rn];
        ulonglong2 b1 = *(const ulonglong2*)&sh[k*132 + rn + 4];
        float4 a0 = *(const float4*)&sWb[k*68 + rm];
        float4 a1 = *(const float4*)&sWb[k*68 + rm + 4];
        float av[8] = {a0.x,a0.y,a0.z,a0.w,a1.x,a1.y,a1.z,a1.w};
        #pragma unroll
        for (int i = 0; i < 8; i++) {
            uint64_t ap = pk2(av[i], av[i]);
            fma2(acc[i][0], ap, b0.x); fma2(acc[i][1], ap, b0.y);
            fma2(acc[i][2], ap, b1.x); fma2(acc[i][3], ap, b1.y);
        }
    }
    // epilogue: + bias + skip, write g_x and sx
    #pragma unroll
    for (int i = 0; i < 8; i++) {
        int row = rm + i;
        float bs = bt2_b[row];
        float v[8];
        #pragma unroll
        for (int j = 0; j < 4; j++) unpk2(acc[i][j], v[2*j], v[2*j+1]);
        float4 s0 = *(const float4*)(g_hx + ((size_t)(b*128+64+row))*NN + bn0 + rn);
        float4 s1 = *(const float4*)(g_hx + ((size_t)(b*128+64+row))*NN + bn0 + rn + 4);
        v[0]+=bs+s0.x; v[1]+=bs+s0.y; v[2]+=bs+s0.z; v[3]+=bs+s0.w;
        v[4]+=bs+s1.x; v[5]+=bs+s1.y; v[6]+=bs+s1.z; v[7]+=bs+s1.w;
        *(float4*)(g_x + ((size_t)(b*64+row))*NN + bn0 + rn)     = make_float4(v[0],v[1],v[2],v[3]);
        *(float4*)(g_x + ((size_t)(b*64+row))*NN + bn0 + rn + 4) = make_float4(v[4],v[5],v[6],v[7]);
        *(float4*)&sx[row*132 + rn]     = make_float4(v[0],v[1],v[2],v[3]);
        *(float4*)&sx[row*132 + rn + 4] = make_float4(v[4],v[5],v[6],v[7]);
    }
    __syncthreads();

    // phase2: qkv parts, staged transpose out
    for (int p = 0; p < 3; ++p) {
        #pragma unroll
        for (int i = 0; i < 8; i++) { int t = tid + i*128; int k = t>>4, m4 = (t&15)*4;
            *(float4*)&sWb[k*68 + m4] = *(const float4*)(g_w_qkv + k*192 + p*64 + m4); }
        __syncthreads();
        uint64_t ac[8][4];
        #pragma unroll
        for (int i = 0; i < 8; i++)
            #pragma unroll
            for (int j = 0; j < 4; j++) ac[i][j] = 0ull;
        #pragma unroll 4
        for (int k = 0; k < 64; ++k) {
            ulonglong2 b0 = *(const ulonglong2*)&sx[k*132 + rn];
            ulonglong2 b1 = *(const ulonglong2*)&sx[k*132 + rn + 4];
            float4 a0 = *(const float4*)&sWb[k*68 + rm];
            float4 a1 = *(const float4*)&sWb[k*68 + rm + 4];
            float av[8] = {a0.x,a0.y,a0.z,a0.w,a1.x,a1.y,a1.z,a1.w};
            #pragma unroll
            for (int i = 0; i < 8; i++) {
                uint64_t ap = pk2(av[i], av[i]);
                fma2(ac[i][0], ap, b0.x); fma2(ac[i][1], ap, b0.y);
                fma2(ac[i][2], ap, b1.x); fma2(ac[i][3], ap, b1.y);
            }
        }
        __syncthreads();   // sh free
        #pragma unroll
        for (int i = 0; i < 8; i++) {
            int row = rm + i;
            float bs = g_b_qkv[p*64 + row];
            float v[8];
            #pragma unroll
            for (int j = 0; j < 4; j++) unpk2(ac[i][j], v[2*j], v[2*j+1]);
            #pragma unroll
            for (int j = 0; j < 8; j++) sh[row*132 + rn + j] = v[j] + bs;
        }
        __syncthreads();
        // transpose out: qkvt[(b, n)][p*64 + c]
        int c4 = (tid & 15) * 4;
        int nb_ = tid >> 4;
        #pragma unroll
        for (int pass = 0; pass < 16; ++pass) {
            int nl = pass*8 + nb_;
            float4 o = make_float4(sh[(c4+0)*132 + nl], sh[(c4+1)*132 + nl],
                                   sh[(c4+2)*132 + nl], sh[(c4+3)*132 + nl]);
            *(float4*)(g_qkvt + ((size_t)(b*NN) + bn0 + nl)*192 + p*64 + c4) = o;
        }
        __syncthreads();
    }
}

// ---------------- fused rel_xyz + fd1 ----------------
__global__ void posenc1(const float* __restrict__ xyz, const float* __restrict__ fd1_w)
{
    __shared__ float srel[3][32];
    int b = blockIdx.y;
    int base = blockIdx.x * 32;
    int tid = threadIdx.x;
    if (tid < 32) {
        int col = base + tid;
        int n = col >> 4, j = col & 15;
        int id = g_idx[b*KK*NN + j*NN + n];
        const float* xb = xyz + b*3*NN;
        srel[0][tid] = xb[n]      - xb[id];
        srel[1][tid] = xb[NN+n]   - xb[NN+id];
        srel[2][tid] = xb[2*NN+n] - xb[2*NN+id];
    }
    __syncthreads();
    int lane = tid & 31, w = tid >> 5;
    float rx = srel[0][lane], ry = srel[1][lane], rz = srel[2][lane];
    #pragma unroll
    for (int it = 0; it < 8; ++it) {
        int m = it*8 + w;
        float v = fd1_w[m*3]*rx + fd1_w[m*3+1]*ry + fd1_w[m*3+2]*rz;
        v = fmaxf(v * g_fold[m] + g_fold[64+m], 0.f);
        g_t1[(size_t)(b*64+m)*NK + base + lane] = v;
    }
}

// ---------------- fused fd2 GEMM + G/Vrel build ----------------
// grid (256,1,BB), 128 threads. smem: sW[64][68] + sT[64][132]
__global__ void __launch_bounds__(128) fd2gv_kernel(const float* __restrict__ fd2_b)
{
    extern __shared__ __align__(16) float dynA[];
    float* sW = dynA;           // [64][68]
    float* sT = dynA + 64*68;   // [64][132]
    int tid = threadIdx.x;
    int b = blockIdx.z;
    int bn0 = blockIdx.x * 128;
    int tx = tid & 15, ty = tid >> 4;
    int rn = tx*8, rm = ty*8;

    #pragma unroll
    for (int i = 0; i < 8; i++) { int t = tid + i*128; int k = t>>4, m4 = (t&15)*4;
        *(float4*)&sW[k*68 + m4] = *(const float4*)(g_w_fd2 + k*64 + m4); }
    #pragma unroll
    for (int i = 0; i < 16; i++) { int t = tid + i*128; int k = t>>5, f = (t&31)*4;
        *(float4*)&sT[k*132 + f] = *(const float4*)(g_t1 + ((size_t)(b*64+k))*NK + bn0 + f); }
    __syncthreads();

    uint64_t acc[8][4];
    #pragma unroll
    for (int i = 0; i < 8; i++)
        #pragma unroll
        for (int j = 0; j < 4; j++) acc[i][j] = 0ull;
    #pragma unroll 4
    for (int k = 0; k < 64; ++k) {
        ulonglong2 b0 = *(const ulonglong2*)&sT[k*132 + rn];
        ulonglong2 b1 = *(const ulonglong2*)&sT[k*132 + rn + 4];
        float4 a0 = *(const float4*)&sW[k*68 + rm];
        float4 a1 = *(const float4*)&sW[k*68 + rm + 4];
        float av[8] = {a0.x,a0.y,a0.z,a0.w,a1.x,a1.y,a1.z,a1.w};
        #pragma unroll
        for (int i = 0; i < 8; i++) {
            uint64_t ap = pk2(av[i], av[i]);
            fma2(acc[i][0], ap, b0.x); fma2(acc[i][1], ap, b0.y);
            fma2(acc[i][2], ap, b1.x); fma2(acc[i][3], ap, b1.y);
        }
    }

    // epilogue: pos = acc + bias; G = q - k + pos; vr = v + pos
    int col0 = bn0 + rn;
    int n = col0 >> 4, j0 = col0 & 15;
    float qv[8], bs[8];
    const float* qp = g_qkvt + ((size_t)b*NN + n)*192 + rm;
    *(float4*)&qv[0] = *(const float4*)qp;
    *(float4*)&qv[4] = *(const float4*)(qp + 4);
    #pragma unroll
    for (int i = 0; i < 8; i++) bs[i] = fd2_b[rm + i];

    #pragma unroll
    for (int g = 0; g < 2; ++g) {
        float ka[4][8], va[4][8];
        #pragma unroll
        for (int jj = 0; jj < 4; jj++) {
            int id = g_idx[b*KK*NN + (j0 + g*4 + jj)*NN + n];
            const float* kp = g_qkvt + ((size_t)b*NN + id)*192 + 64 + rm;
            *(float4*)&ka[jj][0] = *(const float4*)kp;
            *(float4*)&ka[jj][4] = *(const float4*)(kp + 4);
            *(float4*)&va[jj][0] = *(const float4*)(kp + 64);
            *(float4*)&va[jj][4] = *(const float4*)(kp + 68);
        }
        #pragma unroll
        for (int i = 0; i < 8; i++) {
            float p0,p1,p2,p3;
            unpk2(acc[i][2*g],   p0, p1);
            unpk2(acc[i][2*g+1], p2, p3);
            p0 += bs[i]; p1 += bs[i]; p2 += bs[i]; p3 += bs[i];
            size_t off = ((size_t)(b*64 + rm + i))*NK + col0 + g*4;
            *(float4*)(g_G  + off) = make_float4(qv[i]-ka[0][i]+p0, qv[i]-ka[1][i]+p1,
                                                 qv[i]-ka[2][i]+p2, qv[i]-ka[3][i]+p3);
            *(float4*)(g_vr + off) = make_float4(va[0][i]+p0, va[1][i]+p1,
                                                 va[2][i]+p2, va[3][i]+p3);
        }
    }
}

// ---------------- fused fg1 + relu + fg2 ----------------
// grid (512,1,BB), 256 threads. smem: sG[64][68] + sH[256][68] + sW[4096]
__global__ void __launch_bounds__(256) fgfused_kernel(const float* __restrict__ fg2_b)
{
    extern __shared__ __align__(16) float dynB[];
    float* sG = dynB;                       // [64][68]
    float* sH = dynB + 64*68;               // [256][68]
    float* sW = dynB + 64*68 + 256*68;      // 4096 floats
    int tid = threadIdx.x;
    int b = blockIdx.z;
    int col0 = blockIdx.x * 64;

    #pragma unroll
    for (int i = 0; i < 4; i++) { int t = tid + i*256; int c = t>>4, f4 = (t&15)*4;
        *(float4*)&sG[c*68 + f4] = *(const float4*)(g_G + ((size_t)(b*64+c))*NK + col0 + f4); }
    __syncthreads();

    // phase 1: H = relu(scale * (Wfg1 @ G) + bias), per half of 128 rows
    int tx = tid & 7, ty = tid >> 3;      // 8 x 32
    int rn = tx*8, rm = ty*4;
    int wk = tid >> 5, wm = (tid & 31) * 4;   // W chunk loader: 8 x 128
    for (int half = 0; half < 2; ++half) {
        uint64_t acc[4][4];
        #pragma unroll
        for (int i = 0; i < 4; i++)
            #pragma unroll
            for (int j = 0; j < 4; j++) acc[i][j] = 0ull;
        float4 wr = *(const float4*)(g_w_fg1 + (size_t)wk*256 + half*128 + wm);
        for (int kc = 0; kc < 8; ++kc) {
            __syncthreads();
            *(float4*)&sW[wk*128 + wm] = wr;
            __syncthreads();
            if (kc < 7)
                wr = *(const float4*)(g_w_fg1 + (size_t)((kc+1)*8 + wk)*256 + half*128 + wm);
            #pragma unroll
            for (int k = 0; k < 8; ++k) {
                int kk = kc*8 + k;
                ulonglong2 b0 = *(const ulonglong2*)&sG[kk*68 + rn];
                ulonglong2 b1 = *(const ulonglong2*)&sG[kk*68 + rn + 4];
                float4 a4 = *(const float4*)&sW[k*128 + rm];
                float av[4] = {a4.x, a4.y, a4.z, a4.w};
                #pragma unroll
                for (int i = 0; i < 4; i++) {
                    uint64_t ap = pk2(av[i], av[i]);
                    fma2(acc[i][0], ap, b0.x); fma2(acc[i][1], ap, b0.y);
                    fma2(acc[i][2], ap, b1.x); fma2(acc[i][3], ap, b1.y);
                }
            }
        }
        #pragma unroll
        for (int i = 0; i < 4; i++) {
            int row = half*128 + rm + i;
            float sc = g_fold[128 + row], bb2 = g_fold[384 + row];
            float v[8];
            #pragma unroll
            for (int j = 0; j < 4; j++) unpk2(acc[i][j], v[2*j], v[2*j+1]);
            #pragma unroll
            for (int j = 0; j < 8; j++) v[j] = fmaxf(v[j]*sc + bb2, 0.f);
            *(float4*)&sH[row*68 + rn]     = make_float4(v[0],v[1],v[2],v[3]);
            *(float4*)&sH[row*68 + rn + 4] = make_float4(v[4],v[5],v[6],v[7]);
        }
    }
    __syncthreads();

    // phase 2: at = Wfg2 @ H + bias
    int tx2 = tid & 15, ty2 = tid >> 4;    // 16 x 16
    int rn2 = tx2*4, rm2 = ty2*4;
    uint64_t accB[4][2];
    #pragma unroll
    for (int i = 0; i < 4; i++) { accB[i][0] = 0ull; accB[i][1] = 0ull; }
    for (int kc2 = 0; kc2 < 4; ++kc2) {
        __syncthreads();
        #pragma unroll
        for (int i = 0; i < 4; i++) { int t = tid + i*256; int k = t>>4, m4 = (t&15)*4;
            *(float4*)&sW[k*64 + m4] = *(const float4*)(g_w_fg2 + (size_t)(kc2*64 + k)*64 + m4); }
        __syncthreads();
        #pragma unroll 4
        for (int k = 0; k < 64; ++k) {
            int kk = kc2*64 + k;
            ulonglong2 b2 = *(const ulonglong2*)&sH[kk*68 + rn2];
            float4 a4 = *(const float4*)&sW[k*64 + rm2];
            float av[4] = {a4.x, a4.y, a4.z, a4.w};
            #pragma unroll
            for (int i = 0; i < 4; i++) {
                uint64_t ap = pk2(av[i], av[i]);
                fma2(accB[i][0], ap, b2.x); fma2(accB[i][1], ap, b2.y);
            }
        }
    }
    #pragma unroll
    for (int i = 0; i < 4; i++) {
        int row = rm2 + i;
        float bb = __ldg(fg2_b + row);
        float v0,v1,v2,v3;
        unpk2(accB[i][0], v0, v1);
        unpk2(accB[i][1], v2, v3);
        *(float4*)(g_at + ((size_t)(b*64+row))*NK + col0 + rn2) =
            make_float4(v0+bb, v1+bb, v2+bb, v3+bb);
    }
}

// ---------------- fused ConvT(4,1) + softmax + weighted sum + identity ----------------
__global__ void __launch_bounds__(256) k4_kernel(const float* __restrict__ at_b,
                                                 float* __restrict__ res_out)
{
    __shared__ __align__(16) float s_a[64*16];
    __shared__ float s_v[16*64];
    __shared__ float s_m[16][8];
    __shared__ float s_s[16][8];
    __shared__ float s_out[256];
    int bn = blockIdx.x;
    int b = bn >> 11, n = bn & 2047;
    int tid = threadIdx.x;
    int o = tid & 63, r = tid >> 6;
    int lane = tid & 31, warp = tid >> 5;
    {
        int c = tid >> 2, fq = (tid & 3) * 4;
        size_t base = ((size_t)(b*64 + c)*2048 + n)*16 + fq;
        float4 a4 = *(const float4*)(g_at + base);
        *(float4*)(s_a + c*16 + fq) = a4;
        float4 v4 = *(const float4*)(g_vr + base);
        s_v[(fq+0)*64 + c] = v4.x;
        s_v[(fq+1)*64 + c] = v4.y;
        s_v[(fq+2)*64 + c] = v4.z;
        s_v[(fq+3)*64 + c] = v4.w;
    }
    __syncthreads();

    float bo = at_b[o];
    uint64_t y2[8];
    uint64_t bo2 = pk2(bo, bo);
    #pragma unroll
    for (int f = 0; f < 8; f++) y2[f] = bo2;
    const float* w = g_wT + r*4096 + o;
    #pragma unroll 4
    for (int c = 0; c < 64; c++) {
        uint64_t wp = pk2(w[c*64], w[c*64]);
        const ulonglong2* ap = (const ulonglong2*)(s_a + c*16);
        ulonglong2 q0 = ap[0], q1 = ap[1];
        fma2(y2[0], wp, q0.x); fma2(y2[1], wp, q0.y);
        fma2(y2[2], wp, q1.x); fma2(y2[3], wp, q1.y);
        ulonglong2 q2 = ap[2], q3 = ap[3];
        fma2(y2[4], wp, q2.x); fma2(y2[5], wp, q2.y);
        fma2(y2[6], wp, q3.x); fma2(y2[7], wp, q3.y);
    }
    float y[16];
    #pragma unroll
    for (int f = 0; f < 8; f++) unpk2(y2[f], y[2*f], y[2*f+1]);

    #pragma unroll
    for (int f = 0; f < 16; f++) {
        float m = y[f];
        #pragma unroll
        for (int off = 16; off; off >>= 1) m = fmaxf(m, __shfl_xor_sync(0xffffffffu, m, off));
        if (lane == 0) s_m[f][warp] = m;
    }
    __syncthreads();
    #pragma unroll
    for (int f = 0; f < 16; f++) {
        float m = fmaxf(s_m[f][2*r], s_m[f][2*r+1]);
        float e = __expf(y[f] - m);
        y[f] = e;
        float sm = e;
        #pragma unroll
        for (int off = 16; off; off >>= 1) sm += __shfl_xor_sync(0xffffffffu, sm, off);
        if (lane == 0) s_s[f][warp] = sm;
    }
    __syncthreads();
    float acc = 0.f;
    #pragma unroll
    for (int f = 0; f < 16; f++) {
        float sum = s_s[f][2*r] + s_s[f][2*r+1];
        acc = fmaf(y[f] / sum, s_v[f*64 + o], acc);
    }
    acc += g_x[(size_t)b*131072 + o*2048 + n];
    s_out[o*4 + r] = acc;
    __syncthreads();
    if (tid < 64) {
        float4 ov = *(const float4*)(s_out + tid*4);
        *(float4*)(res_out + (size_t)b*524288 + (size_t)tid*8192 + n*4) = ov;
    }
}

// ---------------- fused m41 + relu + m42 ----------------
// grid (64,1,BB), 128 threads. smem: sWm[64][68] + sres[64][132] + sch[64][132]
__global__ void __launch_bounds__(128) m4_kernel(const float* __restrict__ res,
                                                 const float* __restrict__ m41_b,
                                                 const float* __restrict__ m42_w,
                                                 const float* __restrict__ m42_b,
                                                 float* __restrict__ out)
{
    extern __shared__ __align__(16) float dynD[];
    float* sWm  = dynD;                   // [64][68]
    float* sres = dynD + 64*68;           // [64][132]
    float* sch  = dynD + 64*68 + 64*132;  // [64][132]
    int tid = threadIdx.x;
    int b = blockIdx.z;
    int bn0 = blockIdx.x * 128;
    int tx = tid & 15, ty = tid >> 4;
    int rn = tx*8, rm = ty*8;

    #pragma unroll
    for (int i = 0; i < 8; i++) { int t = tid + i*128; int k = t>>4, m4 = (t&15)*4;
        *(float4*)&sWm[k*68 + m4] = *(const float4*)(g_w_m41 + k*64 + m4); }
    #pragma unroll
    for (int i = 0; i < 16; i++) { int t = tid + i*128; int k = t>>5, f = (t&31)*4;
        *(float4*)&sres[k*132 + f] = *(const float4*)(res + ((size_t)(b*64+k))*8192 + bn0 + f); }
    __syncthreads();

    uint64_t acc[8][4];
    #pragma unroll
    for (int i = 0; i < 8; i++)
        #pragma unroll
        for (int j = 0; j < 4; j++) acc[i][j] = 0ull;
    #pragma unroll 4
    for (int k = 0; k < 64; ++k) {
        ulonglong2 b0 = *(const ulonglong2*)&sres[k*132 + rn];
        ulonglong2 b1 = *(const ulonglong2*)&sres[k*132 + rn + 4];
        float4 a0 = *(const float4*)&sWm[k*68 + rm];
        float4 a1 = *(const float4*)&sWm[k*68 + rm + 4];
        float av[8] = {a0.x,a0.y,a0.z,a0.w,a1.x,a1.y,a1.z,a1.w};
        #pragma unroll
        for (int i = 0; i < 8; i++) {
            uint64_t ap = pk2(av[i], av[i]);
            fma2(acc[i][0], ap, b0.x); fma2(acc[i][1], ap, b0.y);
            fma2(acc[i][2], ap, b1.x); fma2(acc[i][3], ap, b1.y);
        }
    }
    #pragma unroll
    for (int i = 0; i < 8; i++) {
        int row = rm + i;
        float bs = m41_b[row];
        float v[8];
        #pragma unroll
        for (int j = 0; j < 4; j++) unpk2(acc[i][j], v[2*j], v[2*j+1]);
        #pragma unroll
        for (int j = 0; j < 8; j++) sch[row*132 + rn + j] = fmaxf(v[j] + bs, 0.f);
    }
    __syncthreads();
    // stage m42 weights over sWm (dead)
    if (tid < 48) *(float4*)&sWm[tid*4] = *(const float4*)(m42_w + tid*4);
    __syncthreads();

    float a0 = m42_b[0], a1 = m42_b[1], a2 = m42_b[2];
    #pragma unroll 8
    for (int k = 0; k < 64; ++k) {
        float xv = sch[k*132 + tid];
        a0 = fmaf(sWm[k],     xv, a0);
        a1 = fmaf(sWm[64+k],  xv, a1);
        a2 = fmaf(sWm[128+k], xv, a2);
    }
    out[(size_t)(b*3+0)*8192 + bn0 + tid] = a0;
    out[(size_t)(b*3+1)*8192 + bn0 + tid] = a1;
    out[(size_t)(b*3+2)*8192 + bn0 + tid] = a2;
}

// ---------------- launch ----------------
extern "C" void kernel_launch(void* const* d_in, const int* in_sizes, int n_in,
                              void* d_out, int out_size)
{
    const float* feature = (const float*)d_in[0];
    const float* xyz     = (const float*)d_in[1];
    const float* bt1_w = (const float*)d_in[2];  const float* bt1_b = (const float*)d_in[3];
    const float* bt2_w = (const float*)d_in[4];  const float* bt2_b = (const float*)d_in[5];
    const float* bts_w = (const float*)d_in[6];  const float* bts_b = (const float*)d_in[7];
    const float* q_w   = (const float*)d_in[8];  const float* q_b   = (const float*)d_in[9];
    const float* k_w   = (const float*)d_in[10]; const float* k_b   = (const float*)d_in[11];
    const float* v_w   = (const float*)d_in[12]; const float* v_b   = (const float*)d_in[13];
    const float* fd1_w = (const float*)d_in[14]; const float* fd1_b = (const float*)d_in[15];
    const float* fd_g  = (const float*)d_in[16]; const float* fd_bb = (const float*)d_in[17];
    const float* fd2_w = (const float*)d_in[18]; const float* fd2_b = (const float*)d_in[19];
    const float* fg1_w = (const float*)d_in[20]; const float* fg1_b = (const float*)d_in[21];
    const float* fg_g  = (const float*)d_in[22]; const float* fg_bb = (const float*)d_in[23];
    const float* fg2_w = (const float*)d_in[24]; const float* fg2_b = (const float*)d_in[25];
    const float* at_w  = (const float*)d_in[26]; const float* at_b  = (const float*)d_in[27];
    const float* m41_w = (const float*)d_in[28]; const float* m41_b = (const float*)d_in[29];
    const float* m42_w = (const float*)d_in[30]; const float* m42_b = (const float*)d_in[31];

    float *phx, *pwbt1s, *pbbt1s;
    cudaGetSymbolAddress((void**)&phx,   g_hx);
    cudaGetSymbolAddress((void**)&pwbt1s,g_w_bt1s);
    cudaGetSymbolAddress((void**)&pbbt1s,g_b_bt1s);

    float* out = (float*)d_out;
    float* res = out + BB*3*4*NN;

    const int smemA = (64*68 + 64*132) * 4;            // 51200
    const int smemB = (64*68 + 256*68 + 4096) * 4;     // 103424
    const int smemC = (64*68 + 64*132 + 64*132) * 4;   // 84992
    const int smemD = smemC;
    static bool attr_done = false;
    if (!attr_done) {
        cudaFuncSetAttribute(fd2gv_kernel,   cudaFuncAttributeMaxDynamicSharedMemorySize, smemA);
        cudaFuncSetAttribute(fgfused_kernel, cudaFuncAttributeMaxDynamicSharedMemorySize, smemB);
        cudaFuncSetAttribute(bt2qkv_kernel,  cudaFuncAttributeMaxDynamicSharedMemorySize, smemC);
        cudaFuncSetAttribute(m4_kernel,      cudaFuncAttributeMaxDynamicSharedMemorySize, smemD);
        attr_done = true;
    }

    prep_kernel<<<256, 256>>>(fd_g, fd1_b, fd_bb, fg_g, fg1_b, fg_bb, at_w,
                              bt1_w, bt1_b, bts_w, bts_b, bt2_w,
                              q_w, q_b, k_w, k_b, v_w, v_b,
                              fd2_w, fg1_w, fg2_w, m41_w);
    knn_kernel<<<BB*NN/16, 512>>>(xyz);

    gemmT<128,64><<<dim3(32,1,BB),128>>>(pwbt1s, 128, feature, (size_t)480*NN,
        pbbt1s, phx, (size_t)128*NN, 480, NN, 64);
    bt2qkv_kernel<<<dim3(16,1,BB), 128, smemC>>>(bt2_b);

    posenc1<<<dim3(NK/32, BB), 256>>>(xyz, fd1_w);
    fd2gv_kernel<<<dim3(256,1,BB), 128, smemA>>>(fd2_b);

    fgfused_kernel<<<dim3(512,1,BB), 256, smemB>>>(fg2_b);

    k4_kernel<<<BB*NN, 256>>>(at_b, res);

    m4_kernel<<<dim3(64,1,BB), 128, smemD>>>(res, m41_b, m42_w, m42_b, out);
}

// round 6
// speedup vs baseline: 1.6675x; 1.1078x over previous
#include <cuda_runtime.h>
#include <cstdint>

#define BB 4
#define NN 2048
#define KK 16
#define DD 64
#define NK (NN*KK)
#define EPSV 1e-5f

// ---------------- f32x2 packed FMA helpers ----------------
__device__ __forceinline__ uint64_t pk2(float lo, float hi){
    uint64_t r;
    asm("mov.b64 %0, {%1, %2};" : "=l"(r) : "r"(__float_as_uint(lo)), "r"(__float_as_uint(hi)));
    return r;
}
__device__ __forceinline__ void fma2(uint64_t& d, uint64_t a, uint64_t b){
    asm("fma.rn.f32x2 %0, %1, %2, %0;" : "+l"(d) : "l"(a), "l"(b));
}
__device__ __forceinline__ void unpk2(uint64_t v, float& lo, float& hi){
    uint32_t l, h;
    asm("mov.b64 {%0, %1}, %2;" : "=r"(l), "=r"(h) : "l"(v));
    lo = __uint_as_float(l); hi = __uint_as_float(h);
}

// ---------------- scratch ----------------
__device__ float g_hx  [BB*128*NN];
__device__ float g_x   [BB*DD*NN];
__device__ float g_qkvt[BB*NN*192];
__device__ int   g_idx [BB*KK*NN];
__device__ float g_G   [BB*DD*NK];
__device__ float g_vr  [BB*DD*NK];
__device__ float g_at  [BB*DD*NK];
__device__ float g_fold[640];     // [128:384) s_fg, [384:640) b_fg
__device__ float g_fd1f[256];     // folded fd1: w0,w1,w2,b
__device__ float g_wT  [4*64*64];
__device__ float g_w_bt1s[480*128];
__device__ float g_b_bt1s[128];
__device__ float g_w_bt2 [64*64];
__device__ float g_w_qkv [64*192];
__device__ float g_b_qkv [192];
__device__ float g_w_fd2 [64*64];
__device__ float g_w_fg1 [64*256];
__device__ float g_w_fg2 [256*64];
__device__ float g_w_m41 [64*64];

// ---------------- prep ----------------
__global__ void prep_kernel(const float* __restrict__ fd_g, const float* __restrict__ fd1_b,
                            const float* __restrict__ fd_bb,
                            const float* __restrict__ fg_g, const float* __restrict__ fg1_b,
                            const float* __restrict__ fg_bb,
                            const float* __restrict__ at_w, const float* __restrict__ fd1_w,
                            const float* __restrict__ bt1_w, const float* __restrict__ bt1_b,
                            const float* __restrict__ bts_w, const float* __restrict__ bts_b,
                            const float* __restrict__ bt2_w,
                            const float* __restrict__ q_w, const float* __restrict__ q_b,
                            const float* __restrict__ k_w, const float* __restrict__ k_b,
                            const float* __restrict__ v_w, const float* __restrict__ v_b,
                            const float* __restrict__ fd2_w,
                            const float* __restrict__ fg1_w, const float* __restrict__ fg2_w,
                            const float* __restrict__ m41_w)
{
    int t = blockIdx.x * blockDim.x + threadIdx.x;
    float inv = rsqrtf(1.f + EPSV);
    if (t < 64) {
        float s = fd_g[t]*inv;
        g_fd1f[t]       = fd1_w[t*3]   * s;
        g_fd1f[64+t]    = fd1_w[t*3+1] * s;
        g_fd1f[128+t]   = fd1_w[t*3+2] * s;
        g_fd1f[192+t]   = fd1_b[t]*s + fd_bb[t];
    }
    if (t < 256) { float s = fg_g[t]*inv; g_fold[128+t] = s; g_fold[384+t] = fg1_b[t]*s + fg_bb[t]; }
    if (t < 16384) {
        int r = t & 3, o = (t >> 2) & 63, c = t >> 8;
        g_wT[r*4096 + c*64 + o] = at_w[t];
        { int k = t >> 8, m = t & 255; g_w_fg1[k*256 + m] = fg1_w[m*64 + k]; }
        { int k = t >> 6, m = t & 63;  g_w_fg2[k*64 + m]  = fg2_w[m*256 + k]; }
    }
    if (t < 61440) { int k = t >> 7, m = t & 127;
        g_w_bt1s[t] = (m < 64) ? bt1_w[m*480 + k] : bts_w[(m-64)*480 + k]; }
    if (t < 128) g_b_bt1s[t] = (t < 64) ? bt1_b[t] : bts_b[t-64];
    if (t < 12288) { int k = t / 192, m = t % 192;
        g_w_qkv[t] = (m < 64) ? q_w[m*64+k] : (m < 128 ? k_w[(m-64)*64+k] : v_w[(m-128)*64+k]); }
    if (t < 192) g_b_qkv[t] = (t < 64) ? q_b[t] : (t < 128 ? k_b[t-64] : v_b[t-128]);
    if (t < 4096) { int k = t >> 6, m = t & 63;
        g_w_bt2[t] = bt2_w[m*64+k];
        g_w_fd2[t] = fd2_w[m*64+k];
        g_w_m41[t] = m41_w[m*64+k]; }
}

// ---------------- KNN ----------------
__global__ void knn_kernel(const float* __restrict__ xyz)
{
    __shared__ float sx[NN], sy[NN], sz[NN], ssq[NN];
    int b  = blockIdx.x >> 7;
    int n0 = (blockIdx.x & 127) * 16;
    const float* xb = xyz + b*3*NN;
    for (int m = threadIdx.x; m < NN; m += blockDim.x) {
        float px = xb[m], py = xb[NN+m], pz = xb[2*NN+m];
        sx[m]=px; sy[m]=py; sz[m]=pz; ssq[m] = px*px + py*py + pz*pz;
    }
    __syncthreads();
    int warp = threadIdx.x >> 5, lane = threadIdx.x & 31;
    int n = n0 + warp;
    float px = sx[n], py = sy[n], pz = sz[n], sqn = ssq[n];

    float bv[17]; int bi[17];
    #pragma unroll
    for (int i = 0; i < 17; i++) { bv[i] = 3.4e38f; bi[i] = 0x7fffffff; }
    for (int m = lane; m < NN; m += 32) {
        float d2 = sqn + ssq[m] - 2.f*(px*sx[m] + py*sy[m] + pz*sz[m]);
        if (d2 < bv[16]) {
            bv[16] = d2; bi[16] = m;
            #pragma unroll
            for (int s = 16; s > 0; --s)
                if (bv[s] < bv[s-1]) {
                    float tv = bv[s]; bv[s] = bv[s-1]; bv[s-1] = tv;
                    int   ti = bi[s]; bi[s] = bi[s-1]; bi[s-1] = ti;
                }
        }
    }
    for (int t = 0; t < 17; ++t) {
        float hv = bv[0]; int hi = bi[0];
        float v = hv; int id = hi;
        #pragma unroll
        for (int off = 16; off; off >>= 1) {
            float ov = __shfl_xor_sync(0xffffffffu, v, off);
            int   oi = __shfl_xor_sync(0xffffffffu, id, off);
            if (ov < v || (ov == v && oi < id)) { v = ov; id = oi; }
        }
        if (t > 0 && lane == 0) g_idx[b*KK*NN + (t-1)*NN + n] = id;
        if (hv == v && hi == id) {
            #pragma unroll
            for (int s = 0; s < 16; ++s) { bv[s] = bv[s+1]; bi[s] = bi[s+1]; }
            bv[16] = 3.4e38f; bi[16] = 0x7fffffff;
        }
    }
}

// ---------------- gemmT (bt1s only, K=480) ----------------
template<int BM, int BN>
__global__ void __launch_bounds__((BM/8)*(BN/8))
gemmT(const float* __restrict__ Wt, int ldw,
      const float* __restrict__ X, size_t xbs,
      const float* __restrict__ bias,
      float* __restrict__ C, size_t cbs,
      int Kd, int Nc, int relu_rows)
{
    constexpr int KC = 8;
    constexpr int NTH = (BM/8)*(BN/8);
    constexpr int W4 = KC*BM/4, X4 = KC*BN/4;
    constexpr int WPT = (W4 + NTH - 1)/NTH, XPT = (X4 + NTH - 1)/NTH;
    __shared__ __align__(16) float sW[2][KC][BM];
    __shared__ __align__(16) float sX[2][KC][BN];
    int tid = threadIdx.x;
    int bn0 = blockIdx.x * BN;
    int bm0 = blockIdx.y * BM;
    const float* Xb = X + (size_t)blockIdx.z * xbs;
    float* Cb = C + (size_t)blockIdx.z * cbs;

    float4 wr[WPT], xr[XPT];
    uint64_t acc2[8][4];
    #pragma unroll
    for (int i = 0; i < 8; i++)
        #pragma unroll
        for (int j = 0; j < 4; j++) acc2[i][j] = 0ull;
    int tx = tid % (BN/8), ty = tid / (BN/8);
    int rm = ty*8, rn = tx*8;
    int nch = Kd / KC;

    {
        #pragma unroll
        for (int i = 0; i < WPT; i++) { int t = tid + i*NTH; if (t < W4) {
            int k = t/(BM/4), m4 = t%(BM/4);
            wr[i] = *(const float4*)(Wt + (size_t)k*ldw + bm0 + m4*4); } }
        #pragma unroll
        for (int i = 0; i < XPT; i++) { int t = tid + i*NTH; if (t < X4) {
            int k = t/(BN/4), n4 = t%(BN/4);
            xr[i] = *(const float4*)(Xb + (size_t)k*Nc + bn0 + n4*4); } }
        #pragma unroll
        for (int i = 0; i < WPT; i++) { int t = tid + i*NTH; if (t < W4) {
            int k = t/(BM/4), m4 = t%(BM/4); *(float4*)&sW[0][k][m4*4] = wr[i]; } }
        #pragma unroll
        for (int i = 0; i < XPT; i++) { int t = tid + i*NTH; if (t < X4) {
            int k = t/(BN/4), n4 = t%(BN/4); *(float4*)&sX[0][k][n4*4] = xr[i]; } }
    }
    __syncthreads();

    for (int c = 0; c < nch; ++c) {
        if (c + 1 < nch) {
            int k0 = (c+1)*KC;
            #pragma unroll
            for (int i = 0; i < WPT; i++) { int t = tid + i*NTH; if (t < W4) {
                int k = t/(BM/4), m4 = t%(BM/4);
                wr[i] = *(const float4*)(Wt + (size_t)(k0+k)*ldw + bm0 + m4*4); } }
            #pragma unroll
            for (int i = 0; i < XPT; i++) { int t = tid + i*NTH; if (t < X4) {
                int k = t/(BN/4), n4 = t%(BN/4);
                xr[i] = *(const float4*)(Xb + (size_t)(k0+k)*Nc + bn0 + n4*4); } }
        }
        int buf = c & 1;
        #pragma unroll
        for (int k = 0; k < KC; ++k) {
            ulonglong2 bq0 = *(const ulonglong2*)&sX[buf][k][rn];
            ulonglong2 bq1 = *(const ulonglong2*)&sX[buf][k][rn+4];
            uint64_t bp[4] = {bq0.x, bq0.y, bq1.x, bq1.y};
            float4 a0 = *(const float4*)&sW[buf][k][rm];
            float4 a1 = *(const float4*)&sW[buf][k][rm+4];
            float av[8] = {a0.x,a0.y,a0.z,a0.w,a1.x,a1.y,a1.z,a1.w};
            #pragma unroll
            for (int i = 0; i < 8; i++) {
                uint64_t ap = pk2(av[i], av[i]);
                #pragma unroll
                for (int j = 0; j < 4; j++) fma2(acc2[i][j], ap, bp[j]);
            }
        }
        if (c + 1 < nch) {
            int nb = (c+1) & 1;
            #pragma unroll
            for (int i = 0; i < WPT; i++) { int t = tid + i*NTH; if (t < W4) {
                int k = t/(BM/4), m4 = t%(BM/4); *(float4*)&sW[nb][k][m4*4] = wr[i]; } }
            #pragma unroll
            for (int i = 0; i < XPT; i++) { int t = tid + i*NTH; if (t < X4) {
                int k = t/(BN/4), n4 = t%(BN/4); *(float4*)&sX[nb][k][n4*4] = xr[i]; } }
        }
        __syncthreads();
    }

    #pragma unroll
    for (int i = 0; i < 8; i++) {
        int row = bm0 + rm + i;
        float bs = bias[row];
        bool rl = row < relu_rows;
        float v[8];
        #pragma unroll
        for (int j = 0; j < 4; j++) unpk2(acc2[i][j], v[2*j], v[2*j+1]);
        #pragma unroll
        for (int j = 0; j < 8; j++) {
            float t = v[j] + bs;
            v[j] = rl ? fmaxf(t, 0.f) : t;
        }
        *(float4*)(Cb + (size_t)row*Nc + bn0 + rn)     = make_float4(v[0],v[1],v[2],v[3]);
        *(float4*)(Cb + (size_t)row*Nc + bn0 + rn + 4) = make_float4(v[4],v[5],v[6],v[7]);
    }
}

// ---------------- fused bt2 + qkv + transpose (BN=64, 128 blocks) ----------------
__global__ void __launch_bounds__(128) bt2qkv_kernel(const float* __restrict__ bt2_b)
{
    extern __shared__ __align__(16) float dynC[];
    float* sWb = dynC;                 // [64][68]
    float* sh  = dynC + 64*68;         // [64][68]
    float* sx  = dynC + 2*64*68;       // [64][68]
    int tid = threadIdx.x;
    int b = blockIdx.z;
    int bn0 = blockIdx.x * 64;
    int tx = tid & 7, ty = tid >> 3;
    int rn = tx*8, rm = ty*4;

    #pragma unroll
    for (int i = 0; i < 8; i++) { int t = tid + i*128; int k = t>>4, m4 = (t&15)*4;
        *(float4*)&sWb[k*68 + m4] = *(const float4*)(g_w_bt2 + k*64 + m4); }
    #pragma unroll
    for (int i = 0; i < 8; i++) { int t = tid + i*128; int k = t>>4, f4 = (t&15)*4;
        *(float4*)&sh[k*68 + f4] = *(const float4*)(g_hx + ((size_t)(b*128+k))*NN + bn0 + f4); }
    __syncthreads();

    uint64_t acc[4][4];
    #pragma unroll
    for (int i = 0; i < 4; i++)
        #pragma unroll
        for (int j = 0; j < 4; j++) acc[i][j] = 0ull;
    #pragma unroll 4
    for (int k = 0; k < 64; ++k) {
        ulonglong2 b0 = *(const ulonglong2*)&sh[k*68 + rn];
        ulonglong2 b1 = *(const ulonglong2*)&sh[k*68 + rn + 4];
        float4 a4 = *(const float4*)&sWb[k*68 + rm];
        float av[4] = {a4.x, a4.y, a4.z, a4.w};
        #pragma unroll
        for (int i = 0; i < 4; i++) {
            uint64_t ap = pk2(av[i], av[i]);
            fma2(acc[i][0], ap, b0.x); fma2(acc[i][1], ap, b0.y);
            fma2(acc[i][2], ap, b1.x); fma2(acc[i][3], ap, b1.y);
        }
    }
    #pragma unroll
    for (int i = 0; i < 4; i++) {
        int row = rm + i;
        float bs = bt2_b[row];
        float v[8];
        #pragma unroll
        for (int j = 0; j < 4; j++) unpk2(acc[i][j], v[2*j], v[2*j+1]);
        float4 s0 = *(const float4*)(g_hx + ((size_t)(b*128+64+row))*NN + bn0 + rn);
        float4 s1 = *(const float4*)(g_hx + ((size_t)(b*128+64+row))*NN + bn0 + rn + 4);
        v[0]+=bs+s0.x; v[1]+=bs+s0.y; v[2]+=bs+s0.z; v[3]+=bs+s0.w;
        v[4]+=bs+s1.x; v[5]+=bs+s1.y; v[6]+=bs+s1.z; v[7]+=bs+s1.w;
        *(float4*)(g_x + ((size_t)(b*64+row))*NN + bn0 + rn)     = make_float4(v[0],v[1],v[2],v[3]);
        *(float4*)(g_x + ((size_t)(b*64+row))*NN + bn0 + rn + 4) = make_float4(v[4],v[5],v[6],v[7]);
        *(float4*)&sx[row*68 + rn]     = make_float4(v[0],v[1],v[2],v[3]);
        *(float4*)&sx[row*68 + rn + 4] = make_float4(v[4],v[5],v[6],v[7]);
    }
    __syncthreads();

    for (int p = 0; p < 3; ++p) {
        #pragma unroll
        for (int i = 0; i < 8; i++) { int t = tid + i*128; int k = t>>4, m4 = (t&15)*4;
            *(float4*)&sWb[k*68 + m4] = *(const float4*)(g_w_qkv + k*192 + p*64 + m4); }
        __syncthreads();
        uint64_t ac[4][4];
        #pragma unroll
        for (int i = 0; i < 4; i++)
            #pragma unroll
            for (int j = 0; j < 4; j++) ac[i][j] = 0ull;
        #pragma unroll 4
        for (int k = 0; k < 64; ++k) {
            ulonglong2 b0 = *(const ulonglong2*)&sx[k*68 + rn];
            ulonglong2 b1 = *(const ulonglong2*)&sx[k*68 + rn + 4];
            float4 a4 = *(const float4*)&sWb[k*68 + rm];
            float av[4] = {a4.x, a4.y, a4.z, a4.w};
            #pragma unroll
            for (int i = 0; i < 4; i++) {
                uint64_t ap = pk2(av[i], av[i]);
                fma2(ac[i][0], ap, b0.x); fma2(ac[i][1], ap, b0.y);
                fma2(ac[i][2], ap, b1.x); fma2(ac[i][3], ap, b1.y);
            }
        }
        __syncthreads();
        #pragma unroll
        for (int i = 0; i < 4; i++) {
            int row = rm + i;
            float bs = g_b_qkv[p*64 + row];
            float v[8];
            #pragma unroll
            for (int j = 0; j < 4; j++) unpk2(ac[i][j], v[2*j], v[2*j+1]);
            #pragma unroll
            for (int j = 0; j < 8; j++) sh[row*68 + rn + j] = v[j] + bs;
        }
        __syncthreads();
        int c4 = (tid & 15) * 4;
        int nb_ = tid >> 4;
        #pragma unroll
        for (int pass = 0; pass < 8; ++pass) {
            int nl = pass*8 + nb_;
            float4 o = make_float4(sh[(c4+0)*68 + nl], sh[(c4+1)*68 + nl],
                                   sh[(c4+2)*68 + nl], sh[(c4+3)*68 + nl]);
            *(float4*)(g_qkvt + ((size_t)(b*NN) + bn0 + nl)*192 + p*64 + c4) = o;
        }
        __syncthreads();
    }
}

// ---------------- fused posenc(fd1) + fd2 GEMM + G/Vrel build ----------------
// grid (256,1,BB), 128 threads. smem: sW[64][68] + sT[64][132] + sF[256]
__global__ void __launch_bounds__(128) fd2gv_kernel(const float* __restrict__ xyz,
                                                    const float* __restrict__ fd2_b)
{
    extern __shared__ __align__(16) float dynA[];
    float* sW = dynA;                    // [64][68]
    float* sT = dynA + 64*68;            // [64][132]
    float* sF = dynA + 64*68 + 64*132;   // 256
    int tid = threadIdx.x;
    int b = blockIdx.z;
    int bn0 = blockIdx.x * 128;
    int tx = tid & 15, ty = tid >> 4;
    int rn = tx*8, rm = ty*8;

    #pragma unroll
    for (int i = 0; i < 8; i++) { int t = tid + i*128; int k = t>>4, m4 = (t&15)*4;
        *(float4*)&sW[k*68 + m4] = *(const float4*)(g_w_fd2 + k*64 + m4); }
    sF[tid] = g_fd1f[tid];
    sF[tid+128] = g_fd1f[tid+128];

    // build t1 tile in smem: each thread owns one column
    int col = bn0 + tid;
    int np = col >> 4, jp = col & 15;
    int idg = g_idx[b*KK*NN + jp*NN + np];
    const float* xb = xyz + b*3*NN;
    float rx = xb[np]      - xb[idg];
    float ry = xb[NN+np]   - xb[NN+idg];
    float rz = xb[2*NN+np] - xb[2*NN+idg];
    __syncthreads();
    #pragma unroll 8
    for (int m = 0; m < 64; ++m) {
        float v = sF[m]*rx + sF[64+m]*ry + sF[128+m]*rz + sF[192+m];
        sT[m*132 + tid] = fmaxf(v, 0.f);
    }
    __syncthreads();

    uint64_t acc[8][4];
    #pragma unroll
    for (int i = 0; i < 8; i++)
        #pragma unroll
        for (int j = 0; j < 4; j++) acc[i][j] = 0ull;
    #pragma unroll 4
    for (int k = 0; k < 64; ++k) {
        ulonglong2 b0 = *(const ulonglong2*)&sT[k*132 + rn];
        ulonglong2 b1 = *(const ulonglong2*)&sT[k*132 + rn + 4];
        float4 a0 = *(const float4*)&sW[k*68 + rm];
        float4 a1 = *(const float4*)&sW[k*68 + rm + 4];
        float av[8] = {a0.x,a0.y,a0.z,a0.w,a1.x,a1.y,a1.z,a1.w};
        #pragma unroll
        for (int i = 0; i < 8; i++) {
            uint64_t ap = pk2(av[i], av[i]);
            fma2(acc[i][0], ap, b0.x); fma2(acc[i][1], ap, b0.y);
            fma2(acc[i][2], ap, b1.x); fma2(acc[i][3], ap, b1.y);
        }
    }

    int col0 = bn0 + rn;
    int n = col0 >> 4, j0 = col0 & 15;
    float qv[8], bs[8];
    const float* qp = g_qkvt + ((size_t)b*NN + n)*192 + rm;
    *(float4*)&qv[0] = *(const float4*)qp;
    *(float4*)&qv[4] = *(const float4*)(qp + 4);
    #pragma unroll
    for (int i = 0; i < 8; i++) bs[i] = fd2_b[rm + i];

    #pragma unroll
    for (int g = 0; g < 2; ++g) {
        float ka[4][8], va[4][8];
        #pragma unroll
        for (int jj = 0; jj < 4; jj++) {
            int id = g_idx[b*KK*NN + (j0 + g*4 + jj)*NN + n];
            const float* kp = g_qkvt + ((size_t)b*NN + id)*192 + 64 + rm;
            *(float4*)&ka[jj][0] = *(const float4*)kp;
            *(float4*)&ka[jj][4] = *(const float4*)(kp + 4);
            *(float4*)&va[jj][0] = *(const float4*)(kp + 64);
            *(float4*)&va[jj][4] = *(const float4*)(kp + 68);
        }
        #pragma unroll
        for (int i = 0; i < 8; i++) {
            float p0,p1,p2,p3;
            unpk2(acc[i][2*g],   p0, p1);
            unpk2(acc[i][2*g+1], p2, p3);
            p0 += bs[i]; p1 += bs[i]; p2 += bs[i]; p3 += bs[i];
            size_t off = ((size_t)(b*64 + rm + i))*NK + col0 + g*4;
            *(float4*)(g_G  + off) = make_float4(qv[i]-ka[0][i]+p0, qv[i]-ka[1][i]+p1,
                                                 qv[i]-ka[2][i]+p2, qv[i]-ka[3][i]+p3);
            *(float4*)(g_vr + off) = make_float4(va[0][i]+p0, va[1][i]+p1,
                                                 va[2][i]+p2, va[3][i]+p3);
        }
    }
}

// ---------------- fused fg1 + relu + fg2 (8x8 tiles both phases) ----------------
// grid (512,1,BB), 256 threads. smem: sG[64][68] + sH[256][68] + sW[4096]
__global__ void __launch_bounds__(256) fgfused_kernel(const float* __restrict__ fg2_b)
{
    extern __shared__ __align__(16) float dynB[];
    float* sG = dynB;                       // [64][68]
    float* sH = dynB + 64*68;               // [256][68]
    float* sW = dynB + 64*68 + 256*68;      // 4096 floats
    int tid = threadIdx.x;
    int b = blockIdx.z;
    int col0 = blockIdx.x * 64;

    #pragma unroll
    for (int i = 0; i < 4; i++) { int t = tid + i*256; int c = t>>4, f4 = (t&15)*4;
        *(float4*)&sG[c*68 + f4] = *(const float4*)(g_G + ((size_t)(b*64+c))*NK + col0 + f4); }

    // phase 1: H[256 x 64] = relu(scale * Wfg1 @ G + bias); 8x8 tiles
    int tx = tid & 7, ty = tid >> 3;
    int rn = tx*8, rm = ty*8;
    uint64_t acc[8][4];
    #pragma unroll
    for (int i = 0; i < 8; i++)
        #pragma unroll
        for (int j = 0; j < 4; j++) acc[i][j] = 0ull;
    for (int kc = 0; kc < 4; ++kc) {
        __syncthreads();
        #pragma unroll
        for (int i = 0; i < 4; i++) { int idx = tid + i*256; int k = idx>>6, m4 = (idx&63)*4;
            *(float4*)&sW[k*256 + m4] = *(const float4*)(g_w_fg1 + (size_t)(kc*16+k)*256 + m4); }
        __syncthreads();
        #pragma unroll
        for (int k = 0; k < 16; ++k) {
            int kk = kc*16 + k;
            ulonglong2 b0 = *(const ulonglong2*)&sG[kk*68 + rn];
            ulonglong2 b1 = *(const ulonglong2*)&sG[kk*68 + rn + 4];
            float4 a0 = *(const float4*)&sW[k*256 + rm];
            float4 a1 = *(const float4*)&sW[k*256 + rm + 4];
            float av[8] = {a0.x,a0.y,a0.z,a0.w,a1.x,a1.y,a1.z,a1.w};
            #pragma unroll
            for (int i = 0; i < 8; i++) {
                uint64_t ap = pk2(av[i], av[i]);
                fma2(acc[i][0], ap, b0.x); fma2(acc[i][1], ap, b0.y);
                fma2(acc[i][2], ap, b1.x); fma2(acc[i][3], ap, b1.y);
            }
        }
    }
    #pragma unroll
    for (int i = 0; i < 8; i++) {
        int row = rm + i;
        float sc = g_fold[128 + row], bb2 = g_fold[384 + row];
        float v[8];
        #pragma unroll
        for (int j = 0; j < 4; j++) unpk2(acc[i][j], v[2*j], v[2*j+1]);
        #pragma unroll
        for (int j = 0; j < 8; j++) v[j] = fmaxf(v[j]*sc + bb2, 0.f);
        *(float4*)&sH[row*68 + rn]     = make_float4(v[0],v[1],v[2],v[3]);
        *(float4*)&sH[row*68 + rn + 4] = make_float4(v[4],v[5],v[6],v[7]);
    }

    // phase 2: at[64 x 64] = Wfg2 @ H + bias; 4x4 tiles
    int tx2 = tid & 15, ty2 = tid >> 4;
    int rn2 = tx2*4, rm2 = ty2*4;
    uint64_t accB[4][2];
    #pragma unroll
    for (int i = 0; i < 4; i++) { accB[i][0] = 0ull; accB[i][1] = 0ull; }
    for (int kc2 = 0; kc2 < 4; ++kc2) {
        __syncthreads();
        #pragma unroll
        for (int i = 0; i < 4; i++) { int t = tid + i*256; int k = t>>4, m4 = (t&15)*4;
            *(float4*)&sW[k*64 + m4] = *(const float4*)(g_w_fg2 + (size_t)(kc2*64 + k)*64 + m4); }
        __syncthreads();
        #pragma unroll 4
        for (int k = 0; k < 64; ++k) {
            int kk = kc2*64 + k;
            ulonglong2 b2 = *(const ulonglong2*)&sH[kk*68 + rn2];
            float4 a4 = *(const float4*)&sW[k*64 + rm2];
            float av[4] = {a4.x, a4.y, a4.z, a4.w};
            #pragma unroll
            for (int i = 0; i < 4; i++) {
                uint64_t ap = pk2(av[i], av[i]);
                fma2(accB[i][0], ap, b2.x); fma2(accB[i][1], ap, b2.y);
            }
        }
    }
    #pragma unroll
    for (int i = 0; i < 4; i++) {
        int row = rm2 + i;
        float bb = __ldg(fg2_b + row);
        float v0,v1,v2,v3;
        unpk2(accB[i][0], v0, v1);
        unpk2(accB[i][1], v2, v3);
        *(float4*)(g_at + ((size_t)(b*64+row))*NK + col0 + rn2) =
            make_float4(v0+bb, v1+bb, v2+bb, v3+bb);
    }
}

// ---------------- fused ConvT(4,1) + softmax + weighted sum + identity ----------------
__global__ void __launch_bounds__(256) k4_kernel(const float* __restrict__ at_b,
                                                 float* __restrict__ res_out)
{
    __shared__ __align__(16) float s_a[64*16];
    __shared__ float s_v[16*64];
    __shared__ float s_m[16][8];
    __shared__ float s_s[16][8];
    __shared__ float s_out[256];
    int bn = blockIdx.x;
    int b = bn >> 11, n = bn & 2047;
    int tid = threadIdx.x;
    int o = tid & 63, r = tid >> 6;
    int lane = tid & 31, warp = tid >> 5;
    {
        int c = tid >> 2, fq = (tid & 3) * 4;
        size_t base = ((size_t)(b*64 + c)*2048 + n)*16 + fq;
        float4 a4 = *(const float4*)(g_at + base);
        *(float4*)(s_a + c*16 + fq) = a4;
        float4 v4 = *(const float4*)(g_vr + base);
        s_v[(fq+0)*64 + c] = v4.x;
        s_v[(fq+1)*64 + c] = v4.y;
        s_v[(fq+2)*64 + c] = v4.z;
        s_v[(fq+3)*64 + c] = v4.w;
    }
    __syncthreads();

    float bo = at_b[o];
    uint64_t y2[8];
    uint64_t bo2 = pk2(bo, bo);
    #pragma unroll
    for (int f = 0; f < 8; f++) y2[f] = bo2;
    const float* w = g_wT + r*4096 + o;
    #pragma unroll 4
    for (int c = 0; c < 64; c++) {
        uint64_t wp = pk2(w[c*64], w[c*64]);
        const ulonglong2* ap = (const ulonglong2*)(s_a + c*16);
        ulonglong2 q0 = ap[0], q1 = ap[1];
        fma2(y2[0], wp, q0.x); fma2(y2[1], wp, q0.y);
        fma2(y2[2], wp, q1.x); fma2(y2[3], wp, q1.y);
        ulonglong2 q2 = ap[2], q3 = ap[3];
        fma2(y2[4], wp, q2.x); fma2(y2[5], wp, q2.y);
        fma2(y2[6], wp, q3.x); fma2(y2[7], wp, q3.y);
    }
    float y[16];
    #pragma unroll
    for (int f = 0; f < 8; f++) unpk2(y2[f], y[2*f], y[2*f+1]);

    #pragma unroll
    for (int f = 0; f < 16; f++) {
        float m = y[f];
        #pragma unroll
        for (int off = 16; off; off >>= 1) m = fmaxf(m, __shfl_xor_sync(0xffffffffu, m, off));
        if (lane == 0) s_m[f][warp] = m;
    }
    __syncthreads();
    #pragma unroll
    for (int f = 0; f < 16; f++) {
        float m = fmaxf(s_m[f][2*r], s_m[f][2*r+1]);
        float e = __expf(y[f] - m);
        y[f] = e;
        float sm = e;
        #pragma unroll
        for (int off = 16; off; off >>= 1) sm += __shfl_xor_sync(0xffffffffu, sm, off);
        if (lane == 0) s_s[f][warp] = sm;
    }
    __syncthreads();
    float acc = 0.f;
    #pragma unroll
    for (int f = 0; f < 16; f++) {
        float sum = s_s[f][2*r] + s_s[f][2*r+1];
        acc = fmaf(y[f] / sum, s_v[f*64 + o], acc);
    }
    acc += g_x[(size_t)b*131072 + o*2048 + n];
    s_out[o*4 + r] = acc;
    __syncthreads();
    if (tid < 64) {
        float4 ov = *(const float4*)(s_out + tid*4);
        *(float4*)(res_out + (size_t)b*524288 + (size_t)tid*8192 + n*4) = ov;
    }
}

// ---------------- fused m41 + relu + m42 ----------------
__global__ void __launch_bounds__(128) m4_kernel(const float* __restrict__ res,
                                                 const float* __restrict__ m41_b,
                                                 const float* __restrict__ m42_w,
                                                 const float* __restrict__ m42_b,
                                                 float* __restrict__ out)
{
    extern __shared__ __align__(16) float dynD[];
    float* sWm  = dynD;                   // [64][68]
    float* sres = dynD + 64*68;           // [64][132]
    float* sch  = dynD + 64*68 + 64*132;  // [64][132]
    int tid = threadIdx.x;
    int b = blockIdx.z;
    int bn0 = blockIdx.x * 128;
    int tx = tid & 15, ty = tid >> 4;
    int rn = tx*8, rm = ty*8;

    #pragma unroll
    for (int i = 0; i < 8; i++) { int t = tid + i*128; int k = t>>4, m4 = (t&15)*4;
        *(float4*)&sWm[k*68 + m4] = *(const float4*)(g_w_m41 + k*64 + m4); }
    #pragma unroll
    for (int i = 0; i < 16; i++) { int t = tid + i*128; int k = t>>5, f = (t&31)*4;
        *(float4*)&sres[k*132 + f] = *(const float4*)(res + ((size_t)(b*64+k))*8192 + bn0 + f); }
    __syncthreads();

    uint64_t acc[8][4];
    #pragma unroll
    for (int i = 0; i < 8; i++)
        #pragma unroll
        for (int j = 0; j < 4; j++) acc[i][j] = 0ull;
    #pragma unroll 4
    for (int k = 0; k < 64; ++k) {
        ulonglong2 b0 = *(const ulonglong2*)&sres[k*132 + rn];
        ulonglong2 b1 = *(const ulonglong2*)&sres[k*132 + rn + 4];
        float4 a0 = *(const float4*)&sWm[k*68 + rm];
        float4 a1 = *(const float4*)&sWm[k*68 + rm + 4];
        float av[8] = {a0.x,a0.y,a0.z,a0.w,a1.x,a1.y,a1.z,a1.w};
        #pragma unroll
        for (int i = 0; i < 8; i++) {
            uint64_t ap = pk2(av[i], av[i]);
            fma2(acc[i][0], ap, b0.x); fma2(acc[i][1], ap, b0.y);
            fma2(acc[i][2], ap, b1.x); fma2(acc[i][3], ap, b1.y);
        }
    }
    #pragma unroll
    for (int i = 0; i < 8; i++) {
        int row = rm + i;
        float bs = m41_b[row];
        float v[8];
        #pragma unroll
        for (int j = 0; j < 4; j++) unpk2(acc[i][j], v[2*j], v[2*j+1]);
        #pragma unroll
        for (int j = 0; j < 8; j++) sch[row*132 + rn + j] = fmaxf(v[j] + bs, 0.f);
    }
    __syncthreads();
    if (tid < 48) *(float4*)&sWm[tid*4] = *(const float4*)(m42_w + tid*4);
    __syncthreads();

    float a0 = m42_b[0], a1 = m42_b[1], a2 = m42_b[2];
    #pragma unroll 8
    for (int k = 0; k < 64; ++k) {
        float xv = sch[k*132 + tid];
        a0 = fmaf(sWm[k],     xv, a0);
        a1 = fmaf(sWm[64+k],  xv, a1);
        a2 = fmaf(sWm[128+k], xv, a2);
    }
    out[(size_t)(b*3+0)*8192 + bn0 + tid] = a0;
    out[(size_t)(b*3+1)*8192 + bn0 + tid] = a1;
    out[(size_t)(b*3+2)*8192 + bn0 + tid] = a2;
}

// ---------------- launch ----------------
extern "C" void kernel_launch(void* const* d_in, const int* in_sizes, int n_in,
                              void* d_out, int out_size)
{
    const float* feature = (const float*)d_in[0];
    const float* xyz     = (const float*)d_in[1];
    const float* bt1_w = (const float*)d_in[2];  const float* bt1_b = (const float*)d_in[3];
    const float* bt2_w = (const float*)d_in[4];  const float* bt2_b = (const float*)d_in[5];
    const float* bts_w = (const float*)d_in[6];  const float* bts_b = (const float*)d_in[7];
    const float* q_w   = (const float*)d_in[8];  const float* q_b   = (const float*)d_in[9];
    const float* k_w   = (const float*)d_in[10]; const float* k_b   = (const float*)d_in[11];
    const float* v_w   = (const float*)d_in[12]; const float* v_b   = (const float*)d_in[13];
    const float* fd1_w = (const float*)d_in[14]; const float* fd1_b = (const float*)d_in[15];
    const float* fd_g  = (const float*)d_in[16]; const float* fd_bb = (const float*)d_in[17];
    const float* fd2_w = (const float*)d_in[18]; const float* fd2_b = (const float*)d_in[19];
    const float* fg1_w = (const float*)d_in[20]; const float* fg1_b = (const float*)d_in[21];
    const float* fg_g  = (const float*)d_in[22]; const float* fg_bb = (const float*)d_in[23];
    const float* fg2_w = (const float*)d_in[24]; const float* fg2_b = (const float*)d_in[25];
    const float* at_w  = (const float*)d_in[26]; const float* at_b  = (const float*)d_in[27];
    const float* m41_w = (const float*)d_in[28]; const float* m41_b = (const float*)d_in[29];
    const float* m42_w = (const float*)d_in[30]; const float* m42_b = (const float*)d_in[31];

    float *phx, *pwbt1s, *pbbt1s;
    cudaGetSymbolAddress((void**)&phx,   g_hx);
    cudaGetSymbolAddress((void**)&pwbt1s,g_w_bt1s);
    cudaGetSymbolAddress((void**)&pbbt1s,g_b_bt1s);

    float* out = (float*)d_out;
    float* res = out + BB*3*4*NN;

    const int smemA = (64*68 + 64*132 + 256) * 4;      // 52224
    const int smemB = (64*68 + 256*68 + 4096) * 4;     // 103424
    const int smemC = (3*64*68) * 4;                    // 52224
    const int smemD = (64*68 + 64*132 + 64*132) * 4;   // 84992
    static bool attr_done = false;
    if (!attr_done) {
        cudaFuncSetAttribute(fd2gv_kernel,   cudaFuncAttributeMaxDynamicSharedMemorySize, smemA);
        cudaFuncSetAttribute(fgfused_kernel, cudaFuncAttributeMaxDynamicSharedMemorySize, smemB);
        cudaFuncSetAttribute(bt2qkv_kernel,  cudaFuncAttributeMaxDynamicSharedMemorySize, smemC);
        cudaFuncSetAttribute(m4_kernel,      cudaFuncAttributeMaxDynamicSharedMemorySize, smemD);
        attr_done = true;
    }

    prep_kernel<<<256, 256>>>(fd_g, fd1_b, fd_bb, fg_g, fg1_b, fg_bb, at_w, fd1_w,
                              bt1_w, bt1_b, bts_w, bts_b, bt2_w,
                              q_w, q_b, k_w, k_b, v_w, v_b,
                              fd2_w, fg1_w, fg2_w, m41_w);
    knn_kernel<<<BB*NN/16, 512>>>(xyz);

    gemmT<128,64><<<dim3(32,1,BB),128>>>(pwbt1s, 128, feature, (size_t)480*NN,
        pbbt1s, phx, (size_t)128*NN, 480, NN, 64);
    bt2qkv_kernel<<<dim3(32,1,BB), 128, smemC>>>(bt2_b);

    fd2gv_kernel<<<dim3(256,1,BB), 128, smemA>>>(xyz, fd2_b);

    fgfused_kernel<<<dim3(512,1,BB), 256, smemB>>>(fg2_b);

    k4_kernel<<<BB*NN, 256>>>(at_b, res);

    m4_kernel<<<dim3(64,1,BB), 128, smemD>>>(res, m41_b, m42_w, m42_b, out);
}